// round 1
// baseline (speedup 1.0000x reference)
#include <cuda_runtime.h>

// Problem constants
namespace {
constexpr int Bsz   = 2;
constexpr int Tlen  = 2048;
constexpr int HID   = 1024;
constexpr int HEADS = 16;
constexpr int HDIM  = 64;
constexpr int BT    = Bsz * Tlen;   // 4096 rows total
constexpr int C3    = 3 * HID;      // 3072
}

// Scratch buffers (allocation-free rule: __device__ globals)
__device__ float g_qkv[BT * C3];    // [4096, 3072] qkv projections
__device__ float g_att[BT * HID];   // [4096, 1024] attention output

// ---------------------------------------------------------------------------
// SGEMM + bias: C[M,N] = A[M,K] @ W[K,N] + bias[N]
// 128x128 tile, BK=8, 256 threads, 8x8 register blocking, float4 everywhere.
// Requires M%128==0, N%128==0, K%8==0 (true for all shapes here).
// ---------------------------------------------------------------------------
__global__ __launch_bounds__(256) void sgemm_bias(
    const float* __restrict__ A, const float* __restrict__ W,
    const float* __restrict__ bias, float* __restrict__ Cout,
    int M, int N, int K)
{
    constexpr int BM = 128, BN = 128, BK = 8;
    __shared__ float As[BK][BM];
    __shared__ float Ws[BK][BN];

    const int tid = threadIdx.x;
    const int bm  = blockIdx.y * BM;
    const int bn  = blockIdx.x * BN;
    const int tx  = tid & 15;       // 0..15 -> output cols tx*8..tx*8+7
    const int ty  = tid >> 4;       // 0..15 -> output rows ty*8..ty*8+7

    // load mapping
    const int arow = tid >> 1;            // 0..127
    const int acol = (tid & 1) * 4;       // 0 or 4 (within BK)
    const int wrow = tid >> 5;            // 0..7
    const int wcol = (tid & 31) * 4;      // 0..124

    const float* Ap = A + (size_t)(bm + arow) * K + acol;
    const float* Wp = W + (size_t)wrow * N + bn + wcol;

    float acc[8][8];
    #pragma unroll
    for (int i = 0; i < 8; i++)
        #pragma unroll
        for (int j = 0; j < 8; j++) acc[i][j] = 0.f;

    for (int k0 = 0; k0 < K; k0 += BK) {
        float4 av = *(const float4*)(Ap + k0);
        float4 wv = *(const float4*)(Wp + (size_t)k0 * N);
        As[acol + 0][arow] = av.x;
        As[acol + 1][arow] = av.y;
        As[acol + 2][arow] = av.z;
        As[acol + 3][arow] = av.w;
        *(float4*)&Ws[wrow][wcol] = wv;
        __syncthreads();

        #pragma unroll
        for (int k = 0; k < BK; k++) {
            float a[8], b[8];
            *(float4*)(a)     = *(const float4*)&As[k][ty * 8];
            *(float4*)(a + 4) = *(const float4*)&As[k][ty * 8 + 4];
            *(float4*)(b)     = *(const float4*)&Ws[k][tx * 8];
            *(float4*)(b + 4) = *(const float4*)&Ws[k][tx * 8 + 4];
            #pragma unroll
            for (int i = 0; i < 8; i++)
                #pragma unroll
                for (int j = 0; j < 8; j++)
                    acc[i][j] = fmaf(a[i], b[j], acc[i][j]);
        }
        __syncthreads();
    }

    #pragma unroll
    for (int i = 0; i < 8; i++) {
        const int row = bm + ty * 8 + i;
        float* cp = Cout + (size_t)row * N + bn + tx * 8;
        #pragma unroll
        for (int j = 0; j < 8; j += 4) {
            const int col = bn + tx * 8 + j;
            float4 o;
            o.x = acc[i][j + 0] + bias[col + 0];
            o.y = acc[i][j + 1] + bias[col + 1];
            o.z = acc[i][j + 2] + bias[col + 2];
            o.w = acc[i][j + 3] + bias[col + 3];
            *(float4*)(cp + j) = o;
        }
    }
}

// ---------------------------------------------------------------------------
// Causal flash attention, fp32.
// grid.x = Tlen/128 (query blocks), grid.y = B*HEADS.
// 128 threads; thread t owns query row qb*128+t. q and o live in registers.
// K/V tiles of 64 rows in shared, read broadcast as float4.
// ---------------------------------------------------------------------------
__global__ __launch_bounds__(128) void flash_attn(
    const float* __restrict__ qkv, float* __restrict__ out)
{
    const int qb = blockIdx.x;
    const int b  = blockIdx.y >> 4;     // / HEADS
    const int h  = blockIdx.y & 15;     // % HEADS
    const int t  = threadIdx.x;
    const int row = qb * 128 + t;
    const float* base = qkv + (size_t)b * Tlen * C3;

    float4 q[16], o[16];
    const float4* qp = (const float4*)(base + (size_t)row * C3 + h * HDIM);
    #pragma unroll
    for (int i = 0; i < 16; i++) q[i] = qp[i];
    #pragma unroll
    for (int i = 0; i < 16; i++) o[i] = make_float4(0.f, 0.f, 0.f, 0.f);

    float m = -1e30f, l = 0.f;

    __shared__ float4 Ks[64][16];
    __shared__ float4 Vs[64][16];

    const int nkb = 2 * qb + 2;   // key tiles needed for rows in this block
    for (int kb = 0; kb < nkb; kb++) {
        __syncthreads();   // protect previous tile's readers
        const float* kbase = base + (size_t)(kb * 64) * C3 + HID + h * HDIM;
        const float* vbase = kbase + HID;
        #pragma unroll
        for (int i = 0; i < 8; i++) {
            int idx = i * 128 + t;
            int j = idx >> 4, d4 = idx & 15;
            Ks[j][d4] = ((const float4*)(kbase + (size_t)j * C3))[d4];
            Vs[j][d4] = ((const float4*)(vbase + (size_t)j * C3))[d4];
        }
        __syncthreads();

        int jmax = row - kb * 64;        // keys j with kb*64+j <= row
        if (jmax < 0) continue;          // this thread's row sees none of this tile
        if (jmax > 63) jmax = 63;

        #pragma unroll 1
        for (int j = 0; j <= jmax; j++) {
            float s = 0.f;
            #pragma unroll
            for (int d = 0; d < 16; d++) {
                float4 kv = Ks[j][d];
                s = fmaf(q[d].x, kv.x, s);
                s = fmaf(q[d].y, kv.y, s);
                s = fmaf(q[d].z, kv.z, s);
                s = fmaf(q[d].w, kv.w, s);
            }
            s *= 0.125f;   // 1/sqrt(64)

            float p;
            if (s > m) {   // rare path: new running max, rescale state
                float corr = __expf(m - s);
                l *= corr;
                #pragma unroll
                for (int d = 0; d < 16; d++) {
                    o[d].x *= corr; o[d].y *= corr;
                    o[d].z *= corr; o[d].w *= corr;
                }
                m = s;
                p = 1.f;
            } else {
                p = __expf(s - m);
            }
            l += p;
            #pragma unroll
            for (int d = 0; d < 16; d++) {
                float4 vv = Vs[j][d];
                o[d].x = fmaf(p, vv.x, o[d].x);
                o[d].y = fmaf(p, vv.y, o[d].y);
                o[d].z = fmaf(p, vv.z, o[d].z);
                o[d].w = fmaf(p, vv.w, o[d].w);
            }
        }
    }

    const float inv = 1.f / l;
    float4* op = (float4*)(out + (size_t)(b * Tlen + row) * HID + h * HDIM);
    #pragma unroll
    for (int i = 0; i < 16; i++) {
        float4 v = o[i];
        v.x *= inv; v.y *= inv; v.z *= inv; v.w *= inv;
        op[i] = v;
    }
}

// ---------------------------------------------------------------------------
// Launch: QKV GEMM -> flash attention -> proj GEMM
// ---------------------------------------------------------------------------
extern "C" void kernel_launch(void* const* d_in, const int* in_sizes, int n_in,
                              void* d_out, int out_size)
{
    const float* x     = (const float*)d_in[0];
    const float* Wqkv  = (const float*)d_in[1];
    const float* bqkv  = (const float*)d_in[2];
    const float* Wproj = (const float*)d_in[3];
    const float* bproj = (const float*)d_in[4];
    float* out = (float*)d_out;

    float *qkv_p = nullptr, *att_p = nullptr;
    cudaGetSymbolAddress((void**)&qkv_p, g_qkv);
    cudaGetSymbolAddress((void**)&att_p, g_att);

    // 1) qkv = x @ W_qkv + b_qkv        [4096,1024]@[1024,3072]
    dim3 g1(C3 / 128, BT / 128);
    sgemm_bias<<<g1, 256>>>(x, Wqkv, bqkv, qkv_p, BT, C3, HID);

    // 2) causal attention per (b,h)
    dim3 g2(Tlen / 128, Bsz * HEADS);
    flash_attn<<<g2, 128>>>(qkv_p, att_p);

    // 3) out = att @ W_proj + b_proj    [4096,1024]@[1024,1024]
    dim3 g3(HID / 128, BT / 128);
    sgemm_bias<<<g3, 256>>>(att_p, Wproj, bproj, out, BT, HID, HID);
}

// round 5
// speedup vs baseline: 1.6963x; 1.6963x over previous
#include <cuda_runtime.h>
#include <cstdint>

// ---------------------------------------------------------------------------
// Problem constants
// ---------------------------------------------------------------------------
namespace {
constexpr int Bsz   = 2;
constexpr int Tlen  = 2048;
constexpr int HID   = 1024;
constexpr int HEADS = 16;
constexpr int HDIM  = 64;
constexpr int BT    = Bsz * Tlen;   // 4096
constexpr int C3    = 3 * HID;      // 3072
}

// Scratch (__device__ globals per allocation-free rule)
__device__ float g_qkv[BT * C3];      // qkv projections [4096,3072]
__device__ float g_att[BT * HID];     // attention out (tf32-rounded)
__device__ float g_xr[BT * HID];      // x rounded to tf32
__device__ float g_wtqkv[C3 * HID];   // W_qkv^T [3072,1024] K-major, tf32
__device__ float g_wtproj[HID * HID]; // W_proj^T [1024,1024]

// ---------------------------------------------------------------------------
// Helpers
// ---------------------------------------------------------------------------
__device__ __forceinline__ uint32_t smem_u32(const void* p) {
    uint32_t a;
    asm("{ .reg .u64 t; cvta.to.shared.u64 t, %1; cvt.u32.u64 %0, t; }"
        : "=r"(a) : "l"(p));
    return a;
}
__device__ __forceinline__ float rna_tf32(float x) {
    uint32_t r;
    asm("cvt.rna.tf32.f32 %0, %1;" : "=r"(r) : "f"(x));
    return __uint_as_float(r);
}
// packed fp32x2 math (FFMA2 — base sm_100 feature)
__device__ __forceinline__ unsigned long long fma2(unsigned long long a,
                                                   unsigned long long b,
                                                   unsigned long long c) {
    unsigned long long d;
    asm("fma.rn.f32x2 %0, %1, %2, %3;" : "=l"(d) : "l"(a), "l"(b), "l"(c));
    return d;
}
__device__ __forceinline__ unsigned long long mul2(unsigned long long a,
                                                   unsigned long long b) {
    unsigned long long d;
    asm("mul.rn.f32x2 %0, %1, %2;" : "=l"(d) : "l"(a), "l"(b));
    return d;
}
__device__ __forceinline__ unsigned long long pack2(float x, float y) {
    unsigned long long d;
    asm("mov.b64 %0, {%1, %2};" : "=l"(d) : "f"(x), "f"(y));
    return d;
}
__device__ __forceinline__ float2 unpack2(unsigned long long a) {
    float2 f;
    asm("mov.b64 {%0, %1}, %2;" : "=f"(f.x), "=f"(f.y) : "l"(a));
    return f;
}

__device__ __forceinline__ void ldsm4(uint32_t& r0, uint32_t& r1,
                                      uint32_t& r2, uint32_t& r3, uint32_t a) {
    asm volatile("ldmatrix.sync.aligned.m8n8.x4.shared.b16 {%0,%1,%2,%3}, [%4];"
                 : "=r"(r0), "=r"(r1), "=r"(r2), "=r"(r3) : "r"(a));
}
__device__ __forceinline__ void mma_tf32(float* d, const uint32_t* a,
                                         const uint32_t* b) {
    asm volatile(
        "mma.sync.aligned.m16n8k8.row.col.f32.tf32.tf32.f32 "
        "{%0,%1,%2,%3}, {%4,%5,%6,%7}, {%8,%9}, {%0,%1,%2,%3};"
        : "+f"(d[0]), "+f"(d[1]), "+f"(d[2]), "+f"(d[3])
        : "r"(a[0]), "r"(a[1]), "r"(a[2]), "r"(a[3]), "r"(b[0]), "r"(b[1]));
}

// ---------------------------------------------------------------------------
// TF32 mma.sync GEMM:  C[M,N] = A[M,K] @ Bt[N,K]^T + bias[N]
// A, Bt K-major fp32 (pre-rounded to tf32). 128x128x16 tiles, 8 warps,
// warp tile 64x32 via m16n8k8. cp.async double-buffered, swizzled smem,
// conflict-free ldmatrix fragment loads.
// Smem tile: 128 rows x 4 segments(16B); addr = row*64 + (seg^((row>>1)&3))*16.
// ---------------------------------------------------------------------------
constexpr int TILE_BYTES = 128 * 16 * 4;   // 8 KB per operand per stage

__global__ __launch_bounds__(256, 2) void gemm_tf32mma(
    const float* __restrict__ A, const float* __restrict__ Bt,
    const float* __restrict__ bias, float* __restrict__ C,
    int M, int N, int K)
{
    __shared__ __align__(128) char smem[2 * 2 * TILE_BYTES];
    const uint32_t sA = smem_u32(smem);                 // stages 0,1 for A
    const uint32_t sB = sA + 2 * TILE_BYTES;            // stages 0,1 for B

    const int tid = threadIdx.x, lane = tid & 31, wid = tid >> 5;
    const int bm = blockIdx.y * 128, bn = blockIdx.x * 128;
    const int warp_m = (wid & 1) * 64;                  // 2 warp rows
    const int warp_n = (wid >> 1) * 32;                 // 4 warp cols

    // cp.async mapping: 2 segs per thread per operand per iter
    const int ld_row0 = tid >> 2;
    const int ld_seg0 = tid & 3;
    uint32_t dstA[2], dstB[2];
    const float *srcA[2], *srcB[2];
    #pragma unroll
    for (int i = 0; i < 2; i++) {
        int row = ld_row0 + i * 64, seg = ld_seg0;
        uint32_t off = row * 64 + ((seg ^ ((row >> 1) & 3)) * 16);
        dstA[i] = sA + off;
        dstB[i] = sB + off;
        srcA[i] = A + (size_t)(bm + row) * K + seg * 4;
        srcB[i] = Bt + (size_t)(bn + row) * K + seg * 4;
    }

    // ldmatrix lane address components
    uint32_t a_rowoff[4], a_sw[4];
    #pragma unroll
    for (int mt = 0; mt < 4; mt++) {
        int row = warp_m + mt * 16 + (lane & 7) + ((lane >> 3) & 1) * 8;
        a_rowoff[mt] = row * 64;
        a_sw[mt] = (row >> 1) & 3;
    }
    const int a_segbase = (lane >> 4);
    uint32_t b_rowoff[2], b_sw[2];
    #pragma unroll
    for (int np = 0; np < 2; np++) {
        int row = warp_n + np * 16 + ((lane >> 4) & 1) * 8 + (lane & 7);
        b_rowoff[np] = row * 64;
        b_sw[np] = (row >> 1) & 3;
    }
    const int b_segbase = ((lane >> 3) & 1);

    float acc[4][4][4];
    #pragma unroll
    for (int mt = 0; mt < 4; mt++)
        #pragma unroll
        for (int nt = 0; nt < 4; nt++)
            #pragma unroll
            for (int r = 0; r < 4; r++) acc[mt][nt][r] = 0.f;

    const int NIT = K >> 4;

    #pragma unroll
    for (int i = 0; i < 2; i++) {
        asm volatile("cp.async.cg.shared.global [%0], [%1], 16;"
                     :: "r"(dstA[i]), "l"(srcA[i]));
        asm volatile("cp.async.cg.shared.global [%0], [%1], 16;"
                     :: "r"(dstB[i]), "l"(srcB[i]));
    }
    asm volatile("cp.async.commit_group;");

    for (int c = 0; c < NIT; c++) {
        const uint32_t stoff = (c & 1) * TILE_BYTES;
        if (c + 1 < NIT) {
            const uint32_t nstoff = ((c + 1) & 1) * TILE_BYTES;
            const int koff = (c + 1) * 16;
            #pragma unroll
            for (int i = 0; i < 2; i++) {
                asm volatile("cp.async.cg.shared.global [%0], [%1], 16;"
                             :: "r"(dstA[i] + nstoff), "l"(srcA[i] + koff));
                asm volatile("cp.async.cg.shared.global [%0], [%1], 16;"
                             :: "r"(dstB[i] + nstoff), "l"(srcB[i] + koff));
            }
            asm volatile("cp.async.commit_group;");
            asm volatile("cp.async.wait_group 1;");
        } else {
            asm volatile("cp.async.wait_group 0;");
        }
        __syncthreads();

        #pragma unroll
        for (int ks = 0; ks < 2; ks++) {
            uint32_t af[4][4], bf[2][4];
            #pragma unroll
            for (int mt = 0; mt < 4; mt++) {
                uint32_t seg = (2 * ks + a_segbase) ^ a_sw[mt];
                ldsm4(af[mt][0], af[mt][1], af[mt][2], af[mt][3],
                      sA + stoff + a_rowoff[mt] + seg * 16);
            }
            #pragma unroll
            for (int np = 0; np < 2; np++) {
                uint32_t seg = (2 * ks + b_segbase) ^ b_sw[np];
                ldsm4(bf[np][0], bf[np][1], bf[np][2], bf[np][3],
                      sB + stoff + b_rowoff[np] + seg * 16);
            }
            #pragma unroll
            for (int mt = 0; mt < 4; mt++)
                #pragma unroll
                for (int nt = 0; nt < 4; nt++)
                    mma_tf32(acc[mt][nt], af[mt], bf[nt >> 1] + (nt & 1) * 2);
        }
        __syncthreads();
    }

    const int er = lane >> 2, ec = (lane & 3) * 2;
    #pragma unroll
    for (int mt = 0; mt < 4; mt++) {
        const int row0 = bm + warp_m + mt * 16 + er;
        #pragma unroll
        for (int nt = 0; nt < 4; nt++) {
            const int col = bn + warp_n + nt * 8 + ec;
            const float b0 = bias[col], b1 = bias[col + 1];
            float2 v0 = make_float2(acc[mt][nt][0] + b0, acc[mt][nt][1] + b1);
            float2 v1 = make_float2(acc[mt][nt][2] + b0, acc[mt][nt][3] + b1);
            *(float2*)(C + (size_t)row0 * N + col) = v0;
            *(float2*)(C + (size_t)(row0 + 8) * N + col) = v1;
        }
    }
}

// ---------------------------------------------------------------------------
// Causal flash attention, fp32 with packed f32x2 FMAs (FULL head dim:
// 16 ulonglong2 = 64 floats per row — R4 bug was 8 = half the dim).
// Thread t owns query row qb*128+t; K/V tiles (64 rows) in shared.
// Writes output rounded to tf32 (feeds the tf32 proj GEMM).
// ---------------------------------------------------------------------------
__global__ __launch_bounds__(128) void flash_attn(
    const float* __restrict__ qkv, float* __restrict__ out)
{
    const int qb = blockIdx.x;
    const int b  = blockIdx.y >> 4;
    const int h  = blockIdx.y & 15;
    const int t  = threadIdx.x;
    const int row = qb * 128 + t;
    const float* base = qkv + (size_t)b * Tlen * C3;

    ulonglong2 q2[16], o2[16];
    const ulonglong2* qp = (const ulonglong2*)(base + (size_t)row * C3 + h * HDIM);
    #pragma unroll
    for (int i = 0; i < 16; i++) q2[i] = qp[i];
    #pragma unroll
    for (int i = 0; i < 16; i++) { o2[i].x = 0ull; o2[i].y = 0ull; }

    float m = -1e30f, l = 0.f;

    __shared__ ulonglong2 Ks[64][16];
    __shared__ ulonglong2 Vs[64][16];

    const int nkb = 2 * qb + 2;
    for (int kb = 0; kb < nkb; kb++) {
        __syncthreads();
        const float* kbase = base + (size_t)(kb * 64) * C3 + HID + h * HDIM;
        const float* vbase = kbase + HID;
        #pragma unroll
        for (int i = 0; i < 8; i++) {
            int idx = i * 128 + t;           // 1024 = 64 rows * 16 u2
            int j = idx >> 4, d = idx & 15;
            Ks[j][d] = ((const ulonglong2*)(kbase + (size_t)j * C3))[d];
            Vs[j][d] = ((const ulonglong2*)(vbase + (size_t)j * C3))[d];
        }
        __syncthreads();

        int jmax = row - kb * 64;
        if (jmax < 0) continue;
        if (jmax > 63) jmax = 63;

        #pragma unroll 1
        for (int j = 0; j <= jmax; j++) {
            unsigned long long sa = 0ull, sb2 = 0ull;
            #pragma unroll
            for (int d = 0; d < 16; d++) {
                ulonglong2 kv = Ks[j][d];
                sa  = fma2(q2[d].x, kv.x, sa);
                sb2 = fma2(q2[d].y, kv.y, sb2);
            }
            float2 fa = unpack2(sa), fb = unpack2(sb2);
            float s = ((fa.x + fa.y) + (fb.x + fb.y)) * 0.125f;  // 1/sqrt(64)

            float p;
            if (s > m) {  // rare: new running max -> rescale
                float corr = __expf(m - s);
                unsigned long long c2 = pack2(corr, corr);
                l *= corr;
                #pragma unroll
                for (int d = 0; d < 16; d++) {
                    o2[d].x = mul2(o2[d].x, c2);
                    o2[d].y = mul2(o2[d].y, c2);
                }
                m = s;
                p = 1.f;
            } else {
                p = __expf(s - m);
            }
            l += p;
            unsigned long long p2 = pack2(p, p);
            #pragma unroll
            for (int d = 0; d < 16; d++) {
                ulonglong2 vv = Vs[j][d];
                o2[d].x = fma2(p2, vv.x, o2[d].x);
                o2[d].y = fma2(p2, vv.y, o2[d].y);
            }
        }
    }

    const float inv = 1.f / l;
    float* op = out + (size_t)(b * Tlen + row) * HID + h * HDIM;
    #pragma unroll
    for (int i = 0; i < 16; i++) {
        float2 a = unpack2(o2[i].x), c = unpack2(o2[i].y);
        float4 v;
        v.x = rna_tf32(a.x * inv);
        v.y = rna_tf32(a.y * inv);
        v.z = rna_tf32(c.x * inv);
        v.w = rna_tf32(c.y * inv);
        *(float4*)(op + i * 4) = v;
    }
}

// ---------------------------------------------------------------------------
// Pre-passes: round to tf32; transpose W[K][N] -> Wt[N][K] with tf32 round.
// ---------------------------------------------------------------------------
__global__ void round_tf32_kernel(const float* __restrict__ in,
                                  float* __restrict__ out, int n4)
{
    int i = blockIdx.x * blockDim.x + threadIdx.x;
    if (i < n4) {
        float4 v = ((const float4*)in)[i];
        v.x = rna_tf32(v.x); v.y = rna_tf32(v.y);
        v.z = rna_tf32(v.z); v.w = rna_tf32(v.w);
        ((float4*)out)[i] = v;
    }
}

__global__ void transpose_rna(const float* __restrict__ in,
                              float* __restrict__ out, int K, int N)
{
    __shared__ float tile[32][33];
    const int n0 = blockIdx.x * 32, k0 = blockIdx.y * 32;
    const int tx = threadIdx.x, ty = threadIdx.y;
    #pragma unroll
    for (int i = 0; i < 32; i += 8)
        tile[ty + i][tx] = in[(size_t)(k0 + ty + i) * N + n0 + tx];
    __syncthreads();
    #pragma unroll
    for (int i = 0; i < 32; i += 8)
        out[(size_t)(n0 + ty + i) * K + k0 + tx] = rna_tf32(tile[tx][ty + i]);
}

// ---------------------------------------------------------------------------
// Launch
// ---------------------------------------------------------------------------
extern "C" void kernel_launch(void* const* d_in, const int* in_sizes, int n_in,
                              void* d_out, int out_size)
{
    const float* x     = (const float*)d_in[0];
    const float* Wqkv  = (const float*)d_in[1];
    const float* bqkv  = (const float*)d_in[2];
    const float* Wproj = (const float*)d_in[3];
    const float* bproj = (const float*)d_in[4];
    float* out = (float*)d_out;

    float *qkv_p, *att_p, *xr_p, *wtqkv_p, *wtproj_p;
    cudaGetSymbolAddress((void**)&qkv_p,    g_qkv);
    cudaGetSymbolAddress((void**)&att_p,    g_att);
    cudaGetSymbolAddress((void**)&xr_p,     g_xr);
    cudaGetSymbolAddress((void**)&wtqkv_p,  g_wtqkv);
    cudaGetSymbolAddress((void**)&wtproj_p, g_wtproj);

    // 0) round x to tf32
    {
        int n4 = BT * HID / 4;
        round_tf32_kernel<<<(n4 + 255) / 256, 256>>>(x, xr_p, n4);
    }
    // 0b) transpose + round weights: W[K][N] -> Wt[N][K]
    {
        dim3 blk(32, 8);
        transpose_rna<<<dim3(C3 / 32, HID / 32), blk>>>(Wqkv, wtqkv_p, HID, C3);
        transpose_rna<<<dim3(HID / 32, HID / 32), blk>>>(Wproj, wtproj_p, HID, HID);
    }
    // 1) qkv = xr @ WqkvT^T + b   (M=4096, N=3072, K=1024)
    gemm_tf32mma<<<dim3(C3 / 128, BT / 128), 256>>>(
        xr_p, wtqkv_p, bqkv, qkv_p, BT, C3, HID);
    // 2) causal attention
    flash_attn<<<dim3(Tlen / 128, Bsz * HEADS), 128>>>(qkv_p, att_p);
    // 3) out = att @ WprojT^T + b  (M=4096, N=1024, K=1024)
    gemm_tf32mma<<<dim3(HID / 128, BT / 128), 256>>>(
        att_p, wtproj_p, bproj, out, BT, HID, HID);
}

// round 6
// speedup vs baseline: 4.3749x; 2.5791x over previous
#include <cuda_runtime.h>
#include <cstdint>

// ---------------------------------------------------------------------------
// Problem constants
// ---------------------------------------------------------------------------
namespace {
constexpr int Bsz   = 2;
constexpr int Tlen  = 2048;
constexpr int HID   = 1024;
constexpr int HEADS = 16;
constexpr int HDIM  = 64;
constexpr int BT    = Bsz * Tlen;   // 4096
constexpr int C3    = 3 * HID;      // 3072
}

// Scratch (__device__ globals per allocation-free rule)
__device__ float g_qkv[BT * C3];            // qkv projections (tf32-rounded)
__device__ float g_att[BT * HID];           // attention out (tf32-rounded)
__device__ float g_xr[BT * HID];            // x rounded to tf32
__device__ float g_wtqkv[C3 * HID];         // W_qkv^T [3072,1024] K-major tf32
__device__ float g_wtproj[HID * HID];       // W_proj^T [1024,1024]
__device__ float g_vt[Bsz * HEADS * HDIM * Tlen];  // V^T per (b,h): [64][2048]

// ---------------------------------------------------------------------------
// Helpers
// ---------------------------------------------------------------------------
__device__ __forceinline__ uint32_t smem_u32(const void* p) {
    uint32_t a;
    asm("{ .reg .u64 t; cvta.to.shared.u64 t, %1; cvt.u32.u64 %0, t; }"
        : "=r"(a) : "l"(p));
    return a;
}
__device__ __forceinline__ float rna_tf32(float x) {
    uint32_t r;
    asm("cvt.rna.tf32.f32 %0, %1;" : "=r"(r) : "f"(x));
    return __uint_as_float(r);
}
__device__ __forceinline__ void ldsm4(uint32_t& r0, uint32_t& r1,
                                      uint32_t& r2, uint32_t& r3, uint32_t a) {
    asm volatile("ldmatrix.sync.aligned.m8n8.x4.shared.b16 {%0,%1,%2,%3}, [%4];"
                 : "=r"(r0), "=r"(r1), "=r"(r2), "=r"(r3) : "r"(a));
}
__device__ __forceinline__ void mma_tf32(float* d, const uint32_t* a,
                                         const uint32_t* b) {
    asm volatile(
        "mma.sync.aligned.m16n8k8.row.col.f32.tf32.tf32.f32 "
        "{%0,%1,%2,%3}, {%4,%5,%6,%7}, {%8,%9}, {%0,%1,%2,%3};"
        : "+f"(d[0]), "+f"(d[1]), "+f"(d[2]), "+f"(d[3])
        : "r"(a[0]), "r"(a[1]), "r"(a[2]), "r"(a[3]), "r"(b[0]), "r"(b[1]));
}
__device__ __forceinline__ void cpasync16(uint32_t dst, const void* src) {
    asm volatile("cp.async.cg.shared.global [%0], [%1], 16;"
                 :: "r"(dst), "l"(src));
}

// ---------------------------------------------------------------------------
// TF32 mma.sync GEMM (verified R5):  C = A @ Bt^T + bias, optional tf32 round.
// 128x128x16 tiles, 8 warps, cp.async double-buffered, swizzled smem.
// ---------------------------------------------------------------------------
constexpr int TILE_BYTES = 128 * 16 * 4;   // 8 KB per operand per stage

__global__ __launch_bounds__(256, 2) void gemm_tf32mma(
    const float* __restrict__ A, const float* __restrict__ Bt,
    const float* __restrict__ bias, float* __restrict__ C,
    int M, int N, int K, int round_out)
{
    __shared__ __align__(128) char smem[2 * 2 * TILE_BYTES];
    const uint32_t sA = smem_u32(smem);
    const uint32_t sB = sA + 2 * TILE_BYTES;

    const int tid = threadIdx.x, lane = tid & 31, wid = tid >> 5;
    const int bm = blockIdx.y * 128, bn = blockIdx.x * 128;
    const int warp_m = (wid & 1) * 64;
    const int warp_n = (wid >> 1) * 32;

    const int ld_row0 = tid >> 2;
    const int ld_seg0 = tid & 3;
    uint32_t dstA[2], dstB[2];
    const float *srcA[2], *srcB[2];
    #pragma unroll
    for (int i = 0; i < 2; i++) {
        int row = ld_row0 + i * 64, seg = ld_seg0;
        uint32_t off = row * 64 + ((seg ^ ((row >> 1) & 3)) * 16);
        dstA[i] = sA + off;
        dstB[i] = sB + off;
        srcA[i] = A + (size_t)(bm + row) * K + seg * 4;
        srcB[i] = Bt + (size_t)(bn + row) * K + seg * 4;
    }

    uint32_t a_rowoff[4], a_sw[4];
    #pragma unroll
    for (int mt = 0; mt < 4; mt++) {
        int row = warp_m + mt * 16 + (lane & 7) + ((lane >> 3) & 1) * 8;
        a_rowoff[mt] = row * 64;
        a_sw[mt] = (row >> 1) & 3;
    }
    const int a_segbase = (lane >> 4);
    uint32_t b_rowoff[2], b_sw[2];
    #pragma unroll
    for (int np = 0; np < 2; np++) {
        int row = warp_n + np * 16 + ((lane >> 4) & 1) * 8 + (lane & 7);
        b_rowoff[np] = row * 64;
        b_sw[np] = (row >> 1) & 3;
    }
    const int b_segbase = ((lane >> 3) & 1);

    float acc[4][4][4];
    #pragma unroll
    for (int mt = 0; mt < 4; mt++)
        #pragma unroll
        for (int nt = 0; nt < 4; nt++)
            #pragma unroll
            for (int r = 0; r < 4; r++) acc[mt][nt][r] = 0.f;

    const int NIT = K >> 4;

    #pragma unroll
    for (int i = 0; i < 2; i++) {
        cpasync16(dstA[i], srcA[i]);
        cpasync16(dstB[i], srcB[i]);
    }
    asm volatile("cp.async.commit_group;");

    for (int c = 0; c < NIT; c++) {
        const uint32_t stoff = (c & 1) * TILE_BYTES;
        if (c + 1 < NIT) {
            const uint32_t nstoff = ((c + 1) & 1) * TILE_BYTES;
            const int koff = (c + 1) * 16;
            #pragma unroll
            for (int i = 0; i < 2; i++) {
                cpasync16(dstA[i] + nstoff, srcA[i] + koff);
                cpasync16(dstB[i] + nstoff, srcB[i] + koff);
            }
            asm volatile("cp.async.commit_group;");
            asm volatile("cp.async.wait_group 1;");
        } else {
            asm volatile("cp.async.wait_group 0;");
        }
        __syncthreads();

        #pragma unroll
        for (int ks = 0; ks < 2; ks++) {
            uint32_t af[4][4], bf[2][4];
            #pragma unroll
            for (int mt = 0; mt < 4; mt++) {
                uint32_t seg = (2 * ks + a_segbase) ^ a_sw[mt];
                ldsm4(af[mt][0], af[mt][1], af[mt][2], af[mt][3],
                      sA + stoff + a_rowoff[mt] + seg * 16);
            }
            #pragma unroll
            for (int np = 0; np < 2; np++) {
                uint32_t seg = (2 * ks + b_segbase) ^ b_sw[np];
                ldsm4(bf[np][0], bf[np][1], bf[np][2], bf[np][3],
                      sB + stoff + b_rowoff[np] + seg * 16);
            }
            #pragma unroll
            for (int mt = 0; mt < 4; mt++)
                #pragma unroll
                for (int nt = 0; nt < 4; nt++)
                    mma_tf32(acc[mt][nt], af[mt], bf[nt >> 1] + (nt & 1) * 2);
        }
        __syncthreads();
    }

    const int er = lane >> 2, ec = (lane & 3) * 2;
    #pragma unroll
    for (int mt = 0; mt < 4; mt++) {
        const int row0 = bm + warp_m + mt * 16 + er;
        #pragma unroll
        for (int nt = 0; nt < 4; nt++) {
            const int col = bn + warp_n + nt * 8 + ec;
            const float b0 = bias[col], b1 = bias[col + 1];
            float2 v0 = make_float2(acc[mt][nt][0] + b0, acc[mt][nt][1] + b1);
            float2 v1 = make_float2(acc[mt][nt][2] + b0, acc[mt][nt][3] + b1);
            if (round_out) {
                v0.x = rna_tf32(v0.x); v0.y = rna_tf32(v0.y);
                v1.x = rna_tf32(v1.x); v1.y = rna_tf32(v1.y);
            }
            *(float2*)(C + (size_t)row0 * N + col) = v0;
            *(float2*)(C + (size_t)(row0 + 8) * N + col) = v1;
        }
    }
}

// ---------------------------------------------------------------------------
// Tensor-core causal flash attention (tf32 mma, fp32 softmax/accum).
// Block: one (b,h) x 128 q-rows, 8 warps x m16. Key tiles Bc=64,
// double-buffered cp.async. Q staged in smem, frags kept in regs; the Q
// buffer is then reused as warp-private P staging for the PV mma.
// Smem rows are 64 f32 (256B), 16 segs of 16B, swizzle seg^(row&7).
// ---------------------------------------------------------------------------
constexpr int FA_SMEM = 32768 + 2 * 16384 + 2 * 16384;  // Q/P + K x2 + Vt x2

#define FA_OFF(row, seg) ((row) * 256 + (((seg) ^ ((row) & 7)) * 16))

__global__ __launch_bounds__(256) void flash_mma(
    const float* __restrict__ qkv, const float* __restrict__ vt,
    float* __restrict__ out)
{
    extern __shared__ char fsm[];
    const uint32_t sQ = smem_u32(fsm);       // 32KB, later P staging
    const uint32_t sK = sQ + 32768;          // 2 x 16KB
    const uint32_t sV = sQ + 65536;          // 2 x 16KB
    const int tid = threadIdx.x, lane = tid & 31, w = tid >> 5;
    const int qb = gridDim.x - 1 - blockIdx.x;   // heavy blocks first
    const int bh = blockIdx.y;
    const int b = bh >> 4, h = bh & 15;

    const float* qbase  = qkv + (size_t)b * Tlen * C3 + h * HDIM;
    const float* kbase  = qbase + HID;
    const float* vtbase = vt + (size_t)bh * HDIM * Tlen;

    auto loadKV = [&](int kb, int s) {
        const uint32_t kb32 = s * 16384;
        #pragma unroll
        for (int i = 0; i < 4; i++) {
            int idx = i * 256 + tid;
            int row = idx >> 4, seg = idx & 15;
            uint32_t off = FA_OFF(row, seg);
            cpasync16(sK + kb32 + off,
                      kbase + (size_t)(kb * 64 + row) * C3 + seg * 4);
            cpasync16(sV + kb32 + off,
                      vtbase + (size_t)row * Tlen + kb * 64 + seg * 4);
        }
    };

    // Q stage + tile 0 (one commit group)
    #pragma unroll
    for (int i = 0; i < 8; i++) {
        int idx = i * 256 + tid;
        int row = idx >> 4, seg = idx & 15;
        cpasync16(sQ + FA_OFF(row, seg),
                  qbase + (size_t)(qb * 128 + row) * C3 + seg * 4);
    }
    loadKV(0, 0);
    asm volatile("cp.async.commit_group;");
    asm volatile("cp.async.wait_group 0;");
    __syncthreads();

    // A-fragment geometry (Q and P share it; rows are warp-private)
    const int frow = w * 16 + (lane & 7) + ((lane >> 3) & 1) * 8;
    const uint32_t frow_b = frow * 256;
    const int frow_s = frow & 7;
    const int fseg_hi = lane >> 4;           // + 2*ks

    uint32_t qf[8][4];
    #pragma unroll
    for (int ks = 0; ks < 8; ks++) {
        ldsm4(qf[ks][0], qf[ks][1], qf[ks][2], qf[ks][3],
              sQ + frow_b + (((2 * ks + fseg_hi) ^ frow_s) * 16));
        #pragma unroll
        for (int r = 0; r < 4; r++)   // fold softmax scale 1/8 (exact pow2)
            qf[ks][r] = __float_as_uint(__uint_as_float(qf[ks][r]) * 0.125f);
    }

    // B-fragment geometry (K and V^T tiles share it)
    uint32_t browb[4]; int brows[4];
    #pragma unroll
    for (int np = 0; np < 4; np++) {
        int row = np * 16 + ((lane >> 4) & 1) * 8 + (lane & 7);
        browb[np] = row * 256;
        brows[np] = row & 7;
    }
    const int bseg_lo = (lane >> 3) & 1;     // + 2*ks

    float O[8][4];
    #pragma unroll
    for (int nt = 0; nt < 8; nt++)
        #pragma unroll
        for (int r = 0; r < 4; r++) O[nt][r] = 0.f;
    float m0 = -1e30f, m1 = -1e30f, l0 = 0.f, l1 = 0.f;

    const int rw = qb * 128 + w * 16;
    const int nkb = 2 * qb + 2;
    const int c0off = 2 * (lane & 3);
    const int r0g = rw + (lane >> 2);
    const int r1g = r0g + 8;
    const int prow0 = w * 16 + (lane >> 2);
    const int prow1 = prow0 + 8;

    for (int kb = 0; kb < nkb; kb++) {
        const int s = kb & 1;
        if (kb + 1 < nkb) {
            loadKV(kb + 1, 1 - s);
            asm volatile("cp.async.commit_group;");
            asm volatile("cp.async.wait_group 1;");
        } else {
            asm volatile("cp.async.wait_group 0;");
        }
        __syncthreads();

        if (kb * 64 <= rw + 15) {            // warp-uniform
            const uint32_t Kb = sK + s * 16384, Vb = sV + s * 16384;
            float S[8][4];
            #pragma unroll
            for (int nt = 0; nt < 8; nt++)
                #pragma unroll
                for (int r = 0; r < 4; r++) S[nt][r] = 0.f;

            // S = (Q/8) @ K^T
            #pragma unroll
            for (int ks = 0; ks < 8; ks++) {
                uint32_t kf[4][4];
                #pragma unroll
                for (int np = 0; np < 4; np++) {
                    uint32_t seg = (2 * ks + bseg_lo) ^ brows[np];
                    ldsm4(kf[np][0], kf[np][1], kf[np][2], kf[np][3],
                          Kb + browb[np] + seg * 16);
                }
                #pragma unroll
                for (int nt = 0; nt < 8; nt++)
                    mma_tf32(S[nt], qf[ks], kf[nt >> 1] + (nt & 1) * 2);
            }

            // causal mask (diagonal tiles only)
            if (kb * 64 + 63 > rw) {
                #pragma unroll
                for (int nt = 0; nt < 8; nt++) {
                    int c = kb * 64 + nt * 8 + c0off;
                    if (c     > r0g) S[nt][0] = -1e30f;
                    if (c + 1 > r0g) S[nt][1] = -1e30f;
                    if (c     > r1g) S[nt][2] = -1e30f;
                    if (c + 1 > r1g) S[nt][3] = -1e30f;
                }
            }

            // online softmax
            float mx0 = -1e30f, mx1 = -1e30f;
            #pragma unroll
            for (int nt = 0; nt < 8; nt++) {
                mx0 = fmaxf(mx0, fmaxf(S[nt][0], S[nt][1]));
                mx1 = fmaxf(mx1, fmaxf(S[nt][2], S[nt][3]));
            }
            mx0 = fmaxf(mx0, __shfl_xor_sync(0xffffffffu, mx0, 1));
            mx0 = fmaxf(mx0, __shfl_xor_sync(0xffffffffu, mx0, 2));
            mx1 = fmaxf(mx1, __shfl_xor_sync(0xffffffffu, mx1, 1));
            mx1 = fmaxf(mx1, __shfl_xor_sync(0xffffffffu, mx1, 2));
            const float mn0 = fmaxf(m0, mx0), mn1 = fmaxf(m1, mx1);
            const float cr0 = __expf(m0 - mn0), cr1 = __expf(m1 - mn1);
            float sum0 = 0.f, sum1 = 0.f;
            #pragma unroll
            for (int nt = 0; nt < 8; nt++) {
                S[nt][0] = __expf(S[nt][0] - mn0);
                S[nt][1] = __expf(S[nt][1] - mn0);
                S[nt][2] = __expf(S[nt][2] - mn1);
                S[nt][3] = __expf(S[nt][3] - mn1);
                sum0 += S[nt][0] + S[nt][1];
                sum1 += S[nt][2] + S[nt][3];
            }
            sum0 += __shfl_xor_sync(0xffffffffu, sum0, 1);
            sum0 += __shfl_xor_sync(0xffffffffu, sum0, 2);
            sum1 += __shfl_xor_sync(0xffffffffu, sum1, 1);
            sum1 += __shfl_xor_sync(0xffffffffu, sum1, 2);
            l0 = l0 * cr0 + sum0; m0 = mn0;
            l1 = l1 * cr1 + sum1; m1 = mn1;
            #pragma unroll
            for (int nt = 0; nt < 8; nt++) {
                O[nt][0] *= cr0; O[nt][1] *= cr0;
                O[nt][2] *= cr1; O[nt][3] *= cr1;
            }

            // store P (tf32) to warp-private rows of the Q buffer
            #pragma unroll
            for (int nt = 0; nt < 8; nt++) {
                int segp = nt * 2 + ((lane & 3) >> 1);
                uint32_t inseg = ((lane & 3) & 1) * 8;
                uint32_t ad0 = sQ + prow0 * 256 +
                               ((segp ^ (prow0 & 7)) * 16) + inseg;
                uint32_t ad1 = sQ + prow1 * 256 +
                               ((segp ^ (prow1 & 7)) * 16) + inseg;
                float p0 = rna_tf32(S[nt][0]), p1 = rna_tf32(S[nt][1]);
                float p2 = rna_tf32(S[nt][2]), p3 = rna_tf32(S[nt][3]);
                asm volatile("st.shared.v2.f32 [%0], {%1,%2};"
                             :: "r"(ad0), "f"(p0), "f"(p1) : "memory");
                asm volatile("st.shared.v2.f32 [%0], {%1,%2};"
                             :: "r"(ad1), "f"(p2), "f"(p3) : "memory");
            }
            __syncwarp();

            // O += P @ V   (V^T tile: rows=hdim, cols=keys)
            #pragma unroll
            for (int ks = 0; ks < 8; ks++) {
                uint32_t pf[4];
                ldsm4(pf[0], pf[1], pf[2], pf[3],
                      sQ + frow_b + (((2 * ks + fseg_hi) ^ frow_s) * 16));
                uint32_t vf[4][4];
                #pragma unroll
                for (int np = 0; np < 4; np++) {
                    uint32_t seg = (2 * ks + bseg_lo) ^ brows[np];
                    ldsm4(vf[np][0], vf[np][1], vf[np][2], vf[np][3],
                          Vb + browb[np] + seg * 16);
                }
                #pragma unroll
                for (int nt = 0; nt < 8; nt++)
                    mma_tf32(O[nt], pf, vf[nt >> 1] + (nt & 1) * 2);
            }
            __syncwarp();
        }
        __syncthreads();
    }

    const float i0 = 1.f / l0, i1 = 1.f / l1;
    #pragma unroll
    for (int nt = 0; nt < 8; nt++) {
        const int col = h * HDIM + nt * 8 + c0off;
        float2 v0 = make_float2(rna_tf32(O[nt][0] * i0), rna_tf32(O[nt][1] * i0));
        float2 v1 = make_float2(rna_tf32(O[nt][2] * i1), rna_tf32(O[nt][3] * i1));
        *(float2*)(out + (size_t)(b * Tlen + r0g) * HID + col) = v0;
        *(float2*)(out + (size_t)(b * Tlen + r1g) * HID + col) = v1;
    }
}

// ---------------------------------------------------------------------------
// Pre-passes
// ---------------------------------------------------------------------------
__global__ void round_tf32_kernel(const float* __restrict__ in,
                                  float* __restrict__ out, int n4)
{
    int i = blockIdx.x * blockDim.x + threadIdx.x;
    if (i < n4) {
        float4 v = ((const float4*)in)[i];
        v.x = rna_tf32(v.x); v.y = rna_tf32(v.y);
        v.z = rna_tf32(v.z); v.w = rna_tf32(v.w);
        ((float4*)out)[i] = v;
    }
}

__global__ void transpose_rna(const float* __restrict__ in,
                              float* __restrict__ out, int K, int N)
{
    __shared__ float tile[32][33];
    const int n0 = blockIdx.x * 32, k0 = blockIdx.y * 32;
    const int tx = threadIdx.x, ty = threadIdx.y;
    #pragma unroll
    for (int i = 0; i < 32; i += 8)
        tile[ty + i][tx] = in[(size_t)(k0 + ty + i) * N + n0 + tx];
    __syncthreads();
    #pragma unroll
    for (int i = 0; i < 32; i += 8)
        out[(size_t)(n0 + ty + i) * K + k0 + tx] = rna_tf32(tile[tx][ty + i]);
}

// V^T per (b,h): g_qkv V slice [tok][64] -> g_vt [bh][64][Tlen]
__global__ void vt_transpose(const float* __restrict__ qkv,
                             float* __restrict__ vtout)
{
    __shared__ float tile[32][33];
    const int t0 = blockIdx.x * 32, d0 = blockIdx.y * 32, bh = blockIdx.z;
    const int b = bh >> 4, h = bh & 15;
    const int tx = threadIdx.x, ty = threadIdx.y;
    const float* src = qkv + (size_t)b * Tlen * C3 + 2 * HID + h * HDIM;
    #pragma unroll
    for (int i = 0; i < 32; i += 8)
        tile[ty + i][tx] = src[(size_t)(t0 + ty + i) * C3 + d0 + tx];
    __syncthreads();
    float* dst = vtout + (size_t)bh * HDIM * Tlen;
    #pragma unroll
    for (int i = 0; i < 32; i += 8)
        dst[(size_t)(d0 + ty + i) * Tlen + t0 + tx] = tile[tx][ty + i];
}

// ---------------------------------------------------------------------------
// Launch
// ---------------------------------------------------------------------------
extern "C" void kernel_launch(void* const* d_in, const int* in_sizes, int n_in,
                              void* d_out, int out_size)
{
    const float* x     = (const float*)d_in[0];
    const float* Wqkv  = (const float*)d_in[1];
    const float* bqkv  = (const float*)d_in[2];
    const float* Wproj = (const float*)d_in[3];
    const float* bproj = (const float*)d_in[4];
    float* out = (float*)d_out;

    float *qkv_p, *att_p, *xr_p, *wtqkv_p, *wtproj_p, *vt_p;
    cudaGetSymbolAddress((void**)&qkv_p,    g_qkv);
    cudaGetSymbolAddress((void**)&att_p,    g_att);
    cudaGetSymbolAddress((void**)&xr_p,     g_xr);
    cudaGetSymbolAddress((void**)&wtqkv_p,  g_wtqkv);
    cudaGetSymbolAddress((void**)&wtproj_p, g_wtproj);
    cudaGetSymbolAddress((void**)&vt_p,     g_vt);

    cudaFuncSetAttribute(flash_mma,
                         cudaFuncAttributeMaxDynamicSharedMemorySize, FA_SMEM);

    // 0) round x to tf32; transpose+round weights
    {
        int n4 = BT * HID / 4;
        round_tf32_kernel<<<(n4 + 255) / 256, 256>>>(x, xr_p, n4);
        dim3 blk(32, 8);
        transpose_rna<<<dim3(C3 / 32, HID / 32), blk>>>(Wqkv, wtqkv_p, HID, C3);
        transpose_rna<<<dim3(HID / 32, HID / 32), blk>>>(Wproj, wtproj_p, HID, HID);
    }
    // 1) qkv = xr @ Wqkv^T + b, rounded to tf32 for the attention mmas
    gemm_tf32mma<<<dim3(C3 / 128, BT / 128), 256>>>(
        xr_p, wtqkv_p, bqkv, qkv_p, BT, C3, HID, 1);
    // 1b) V^T per (b,h)
    {
        dim3 blk(32, 8);
        vt_transpose<<<dim3(Tlen / 32, HDIM / 32, Bsz * HEADS), blk>>>(qkv_p, vt_p);
    }
    // 2) tensor-core causal flash attention
    flash_mma<<<dim3(Tlen / 128, Bsz * HEADS), 256, FA_SMEM>>>(qkv_p, vt_p, att_p);
    // 3) out = att @ Wproj^T + b (full fp32 epilogue)
    gemm_tf32mma<<<dim3(HID / 128, BT / 128), 256>>>(
        att_p, wtproj_p, bproj, out, BT, HID, HID, 0);
}

// round 7
// speedup vs baseline: 4.5646x; 1.0434x over previous
#include <cuda_runtime.h>
#include <cstdint>

// ---------------------------------------------------------------------------
// Problem constants
// ---------------------------------------------------------------------------
namespace {
constexpr int Bsz   = 2;
constexpr int Tlen  = 2048;
constexpr int HID   = 1024;
constexpr int HEADS = 16;
constexpr int HDIM  = 64;
constexpr int BT    = Bsz * Tlen;   // 4096
constexpr int C3    = 3 * HID;      // 3072
}

// Scratch (__device__ globals per allocation-free rule)
__device__ float g_qkv[BT * C3];            // qkv projections (tf32-rounded)
__device__ float g_att[BT * HID];           // attention out (tf32-rounded)
__device__ float g_xr[BT * HID];            // x rounded to tf32
__device__ float g_wtqkv[C3 * HID];         // W_qkv^T [3072,1024] K-major tf32
__device__ float g_wtproj[HID * HID];       // W_proj^T [1024,1024]
__device__ float g_vt[Bsz * HEADS * HDIM * Tlen];  // V^T per (b,h): [64][2048]

// ---------------------------------------------------------------------------
// Helpers
// ---------------------------------------------------------------------------
__device__ __forceinline__ uint32_t smem_u32(const void* p) {
    uint32_t a;
    asm("{ .reg .u64 t; cvta.to.shared.u64 t, %1; cvt.u32.u64 %0, t; }"
        : "=r"(a) : "l"(p));
    return a;
}
__device__ __forceinline__ float rna_tf32(float x) {
    uint32_t r;
    asm("cvt.rna.tf32.f32 %0, %1;" : "=r"(r) : "f"(x));
    return __uint_as_float(r);
}
__device__ __forceinline__ void ldsm4(uint32_t& r0, uint32_t& r1,
                                      uint32_t& r2, uint32_t& r3, uint32_t a) {
    asm volatile("ldmatrix.sync.aligned.m8n8.x4.shared.b16 {%0,%1,%2,%3}, [%4];"
                 : "=r"(r0), "=r"(r1), "=r"(r2), "=r"(r3) : "r"(a));
}
__device__ __forceinline__ void mma_tf32(float* d, const uint32_t* a,
                                         const uint32_t* b) {
    asm volatile(
        "mma.sync.aligned.m16n8k8.row.col.f32.tf32.tf32.f32 "
        "{%0,%1,%2,%3}, {%4,%5,%6,%7}, {%8,%9}, {%0,%1,%2,%3};"
        : "+f"(d[0]), "+f"(d[1]), "+f"(d[2]), "+f"(d[3])
        : "r"(a[0]), "r"(a[1]), "r"(a[2]), "r"(a[3]), "r"(b[0]), "r"(b[1]));
}
__device__ __forceinline__ void cpasync16(uint32_t dst, const void* src) {
    asm volatile("cp.async.cg.shared.global [%0], [%1], 16;"
                 :: "r"(dst), "l"(src));
}

// ---------------------------------------------------------------------------
// TF32 mma.sync GEMM:  C = A @ Bt^T + bias, optional tf32 round on output.
// 128x128 tile, BK=32, 8 warps (warp tile 64x32), 3-stage cp.async pipeline,
// ONE __syncthreads per K-iteration.
// Smem rows: 32 f32 = 128B = 8 segs(16B); addr = row*128 + ((seg^(row&7))*16).
// Stage = A(16KB) + B(16KB) = 32KB; 3 stages = 96KB dynamic smem.
// ---------------------------------------------------------------------------
constexpr int G_OPER  = 128 * 128;               // 16 KB per operand per stage
constexpr int G_STAGE = 2 * G_OPER;              // 32 KB
constexpr int G_SMEM  = 3 * G_STAGE;             // 96 KB

#define G_OFF(row, seg) ((row) * 128 + ((((seg) ^ ((row) & 7))) * 16))

__global__ __launch_bounds__(256, 2) void gemm_tf32mma(
    const float* __restrict__ A, const float* __restrict__ Bt,
    const float* __restrict__ bias, float* __restrict__ C,
    int M, int N, int K, int round_out)
{
    extern __shared__ __align__(128) char gsm[];
    const uint32_t s0 = smem_u32(gsm);

    const int tid = threadIdx.x, lane = tid & 31, wid = tid >> 5;
    const int bm = blockIdx.y * 128, bn = blockIdx.x * 128;
    const int warp_m = (wid & 1) * 64;
    const int warp_n = (wid >> 1) * 32;

    // cp.async mapping: 4 segs per thread per operand per chunk
    uint32_t ld_off[4];
    const float *srcA[4], *srcB[4];
    #pragma unroll
    for (int i = 0; i < 4; i++) {
        int idx = i * 256 + tid;
        int row = idx >> 3, seg = idx & 7;
        ld_off[i] = G_OFF(row, seg);
        srcA[i] = A + (size_t)(bm + row) * K + seg * 4;
        srcB[i] = Bt + (size_t)(bn + row) * K + seg * 4;
    }
    auto issue = [&](int chunk, int stage) {
        const uint32_t ab = s0 + stage * G_STAGE;
        const uint32_t bb = ab + G_OPER;
        const int koff = chunk * 32;
        #pragma unroll
        for (int i = 0; i < 4; i++) {
            cpasync16(ab + ld_off[i], srcA[i] + koff);
            cpasync16(bb + ld_off[i], srcB[i] + koff);
        }
        asm volatile("cp.async.commit_group;");
    };

    // ldmatrix lane address components
    uint32_t a_rowoff[4]; int a_sw[4];
    #pragma unroll
    for (int mt = 0; mt < 4; mt++) {
        int row = warp_m + mt * 16 + (lane & 7) + ((lane >> 3) & 1) * 8;
        a_rowoff[mt] = row * 128;
        a_sw[mt] = row & 7;
    }
    const int a_segbase = (lane >> 4);              // + 2*ks
    uint32_t b_rowoff[2]; int b_sw[2];
    #pragma unroll
    for (int np = 0; np < 2; np++) {
        int row = warp_n + np * 16 + ((lane >> 4) & 1) * 8 + (lane & 7);
        b_rowoff[np] = row * 128;
        b_sw[np] = row & 7;
    }
    const int b_segbase = ((lane >> 3) & 1);        // + 2*ks

    float acc[4][4][4];
    #pragma unroll
    for (int mt = 0; mt < 4; mt++)
        #pragma unroll
        for (int nt = 0; nt < 4; nt++)
            #pragma unroll
            for (int r = 0; r < 4; r++) acc[mt][nt][r] = 0.f;

    const int NIT = K >> 5;                          // 32 chunks for K=1024

    issue(0, 0);
    issue(1, 1);

    for (int c = 0; c < NIT; c++) {
        if (c < NIT - 1) {
            asm volatile("cp.async.wait_group 1;");
        } else {
            asm volatile("cp.async.wait_group 0;");
        }
        __syncthreads();     // all warps done reading stage (c+2)%3 (iter c-1)
        if (c + 2 < NIT) issue(c + 2, (c + 2) % 3);

        const uint32_t ab = s0 + (c % 3) * G_STAGE;
        const uint32_t bb = ab + G_OPER;
        #pragma unroll
        for (int ks = 0; ks < 4; ks++) {
            uint32_t af[4][4], bf[2][4];
            #pragma unroll
            for (int mt = 0; mt < 4; mt++) {
                int seg = (2 * ks + a_segbase) ^ a_sw[mt];
                ldsm4(af[mt][0], af[mt][1], af[mt][2], af[mt][3],
                      ab + a_rowoff[mt] + seg * 16);
            }
            #pragma unroll
            for (int np = 0; np < 2; np++) {
                int seg = (2 * ks + b_segbase) ^ b_sw[np];
                ldsm4(bf[np][0], bf[np][1], bf[np][2], bf[np][3],
                      bb + b_rowoff[np] + seg * 16);
            }
            #pragma unroll
            for (int mt = 0; mt < 4; mt++)
                #pragma unroll
                for (int nt = 0; nt < 4; nt++)
                    mma_tf32(acc[mt][nt], af[mt], bf[nt >> 1] + (nt & 1) * 2);
        }
    }

    const int er = lane >> 2, ec = (lane & 3) * 2;
    #pragma unroll
    for (int mt = 0; mt < 4; mt++) {
        const int row0 = bm + warp_m + mt * 16 + er;
        #pragma unroll
        for (int nt = 0; nt < 4; nt++) {
            const int col = bn + warp_n + nt * 8 + ec;
            const float b0 = bias[col], b1 = bias[col + 1];
            float2 v0 = make_float2(acc[mt][nt][0] + b0, acc[mt][nt][1] + b1);
            float2 v1 = make_float2(acc[mt][nt][2] + b0, acc[mt][nt][3] + b1);
            if (round_out) {
                v0.x = rna_tf32(v0.x); v0.y = rna_tf32(v0.y);
                v1.x = rna_tf32(v1.x); v1.y = rna_tf32(v1.y);
            }
            *(float2*)(C + (size_t)row0 * N + col) = v0;
            *(float2*)(C + (size_t)(row0 + 8) * N + col) = v1;
        }
    }
}

// ---------------------------------------------------------------------------
// Tensor-core causal flash attention (verified R6). tf32 mma, fp32 softmax.
// ---------------------------------------------------------------------------
constexpr int FA_SMEM = 32768 + 2 * 16384 + 2 * 16384;

#define FA_OFF(row, seg) ((row) * 256 + (((seg) ^ ((row) & 7)) * 16))

__global__ __launch_bounds__(256) void flash_mma(
    const float* __restrict__ qkv, const float* __restrict__ vt,
    float* __restrict__ out)
{
    extern __shared__ char fsm[];
    const uint32_t sQ = smem_u32(fsm);
    const uint32_t sK = sQ + 32768;
    const uint32_t sV = sQ + 65536;
    const int tid = threadIdx.x, lane = tid & 31, w = tid >> 5;
    const int qb = gridDim.x - 1 - blockIdx.x;
    const int bh = blockIdx.y;
    const int b = bh >> 4, h = bh & 15;

    const float* qbase  = qkv + (size_t)b * Tlen * C3 + h * HDIM;
    const float* kbase  = qbase + HID;
    const float* vtbase = vt + (size_t)bh * HDIM * Tlen;

    auto loadKV = [&](int kb, int s) {
        const uint32_t kb32 = s * 16384;
        #pragma unroll
        for (int i = 0; i < 4; i++) {
            int idx = i * 256 + tid;
            int row = idx >> 4, seg = idx & 15;
            uint32_t off = FA_OFF(row, seg);
            cpasync16(sK + kb32 + off,
                      kbase + (size_t)(kb * 64 + row) * C3 + seg * 4);
            cpasync16(sV + kb32 + off,
                      vtbase + (size_t)row * Tlen + kb * 64 + seg * 4);
        }
    };

    #pragma unroll
    for (int i = 0; i < 8; i++) {
        int idx = i * 256 + tid;
        int row = idx >> 4, seg = idx & 15;
        cpasync16(sQ + FA_OFF(row, seg),
                  qbase + (size_t)(qb * 128 + row) * C3 + seg * 4);
    }
    loadKV(0, 0);
    asm volatile("cp.async.commit_group;");
    asm volatile("cp.async.wait_group 0;");
    __syncthreads();

    const int frow = w * 16 + (lane & 7) + ((lane >> 3) & 1) * 8;
    const uint32_t frow_b = frow * 256;
    const int frow_s = frow & 7;
    const int fseg_hi = lane >> 4;

    uint32_t qf[8][4];
    #pragma unroll
    for (int ks = 0; ks < 8; ks++) {
        ldsm4(qf[ks][0], qf[ks][1], qf[ks][2], qf[ks][3],
              sQ + frow_b + (((2 * ks + fseg_hi) ^ frow_s) * 16));
        #pragma unroll
        for (int r = 0; r < 4; r++)
            qf[ks][r] = __float_as_uint(__uint_as_float(qf[ks][r]) * 0.125f);
    }

    uint32_t browb[4]; int brows[4];
    #pragma unroll
    for (int np = 0; np < 4; np++) {
        int row = np * 16 + ((lane >> 4) & 1) * 8 + (lane & 7);
        browb[np] = row * 256;
        brows[np] = row & 7;
    }
    const int bseg_lo = (lane >> 3) & 1;

    float O[8][4];
    #pragma unroll
    for (int nt = 0; nt < 8; nt++)
        #pragma unroll
        for (int r = 0; r < 4; r++) O[nt][r] = 0.f;
    float m0 = -1e30f, m1 = -1e30f, l0 = 0.f, l1 = 0.f;

    const int rw = qb * 128 + w * 16;
    const int nkb = 2 * qb + 2;
    const int c0off = 2 * (lane & 3);
    const int r0g = rw + (lane >> 2);
    const int r1g = r0g + 8;
    const int prow0 = w * 16 + (lane >> 2);
    const int prow1 = prow0 + 8;

    for (int kb = 0; kb < nkb; kb++) {
        const int s = kb & 1;
        if (kb + 1 < nkb) {
            loadKV(kb + 1, 1 - s);
            asm volatile("cp.async.commit_group;");
            asm volatile("cp.async.wait_group 1;");
        } else {
            asm volatile("cp.async.wait_group 0;");
        }
        __syncthreads();

        if (kb * 64 <= rw + 15) {
            const uint32_t Kb = sK + s * 16384, Vb = sV + s * 16384;
            float S[8][4];
            #pragma unroll
            for (int nt = 0; nt < 8; nt++)
                #pragma unroll
                for (int r = 0; r < 4; r++) S[nt][r] = 0.f;

            #pragma unroll
            for (int ks = 0; ks < 8; ks++) {
                uint32_t kf[4][4];
                #pragma unroll
                for (int np = 0; np < 4; np++) {
                    int seg = (2 * ks + bseg_lo) ^ brows[np];
                    ldsm4(kf[np][0], kf[np][1], kf[np][2], kf[np][3],
                          Kb + browb[np] + seg * 16);
                }
                #pragma unroll
                for (int nt = 0; nt < 8; nt++)
                    mma_tf32(S[nt], qf[ks], kf[nt >> 1] + (nt & 1) * 2);
            }

            if (kb * 64 + 63 > rw) {
                #pragma unroll
                for (int nt = 0; nt < 8; nt++) {
                    int c = kb * 64 + nt * 8 + c0off;
                    if (c     > r0g) S[nt][0] = -1e30f;
                    if (c + 1 > r0g) S[nt][1] = -1e30f;
                    if (c     > r1g) S[nt][2] = -1e30f;
                    if (c + 1 > r1g) S[nt][3] = -1e30f;
                }
            }

            float mx0 = -1e30f, mx1 = -1e30f;
            #pragma unroll
            for (int nt = 0; nt < 8; nt++) {
                mx0 = fmaxf(mx0, fmaxf(S[nt][0], S[nt][1]));
                mx1 = fmaxf(mx1, fmaxf(S[nt][2], S[nt][3]));
            }
            mx0 = fmaxf(mx0, __shfl_xor_sync(0xffffffffu, mx0, 1));
            mx0 = fmaxf(mx0, __shfl_xor_sync(0xffffffffu, mx0, 2));
            mx1 = fmaxf(mx1, __shfl_xor_sync(0xffffffffu, mx1, 1));
            mx1 = fmaxf(mx1, __shfl_xor_sync(0xffffffffu, mx1, 2));
            const float mn0 = fmaxf(m0, mx0), mn1 = fmaxf(m1, mx1);
            const float cr0 = __expf(m0 - mn0), cr1 = __expf(m1 - mn1);
            float sum0 = 0.f, sum1 = 0.f;
            #pragma unroll
            for (int nt = 0; nt < 8; nt++) {
                S[nt][0] = __expf(S[nt][0] - mn0);
                S[nt][1] = __expf(S[nt][1] - mn0);
                S[nt][2] = __expf(S[nt][2] - mn1);
                S[nt][3] = __expf(S[nt][3] - mn1);
                sum0 += S[nt][0] + S[nt][1];
                sum1 += S[nt][2] + S[nt][3];
            }
            sum0 += __shfl_xor_sync(0xffffffffu, sum0, 1);
            sum0 += __shfl_xor_sync(0xffffffffu, sum0, 2);
            sum1 += __shfl_xor_sync(0xffffffffu, sum1, 1);
            sum1 += __shfl_xor_sync(0xffffffffu, sum1, 2);
            l0 = l0 * cr0 + sum0; m0 = mn0;
            l1 = l1 * cr1 + sum1; m1 = mn1;
            #pragma unroll
            for (int nt = 0; nt < 8; nt++) {
                O[nt][0] *= cr0; O[nt][1] *= cr0;
                O[nt][2] *= cr1; O[nt][3] *= cr1;
            }

            #pragma unroll
            for (int nt = 0; nt < 8; nt++) {
                int segp = nt * 2 + ((lane & 3) >> 1);
                uint32_t inseg = ((lane & 3) & 1) * 8;
                uint32_t ad0 = sQ + prow0 * 256 +
                               ((segp ^ (prow0 & 7)) * 16) + inseg;
                uint32_t ad1 = sQ + prow1 * 256 +
                               ((segp ^ (prow1 & 7)) * 16) + inseg;
                float p0 = rna_tf32(S[nt][0]), p1 = rna_tf32(S[nt][1]);
                float p2 = rna_tf32(S[nt][2]), p3 = rna_tf32(S[nt][3]);
                asm volatile("st.shared.v2.f32 [%0], {%1,%2};"
                             :: "r"(ad0), "f"(p0), "f"(p1) : "memory");
                asm volatile("st.shared.v2.f32 [%0], {%1,%2};"
                             :: "r"(ad1), "f"(p2), "f"(p3) : "memory");
            }
            __syncwarp();

            #pragma unroll
            for (int ks = 0; ks < 8; ks++) {
                uint32_t pf[4];
                ldsm4(pf[0], pf[1], pf[2], pf[3],
                      sQ + frow_b + (((2 * ks + fseg_hi) ^ frow_s) * 16));
                uint32_t vf[4][4];
                #pragma unroll
                for (int np = 0; np < 4; np++) {
                    int seg = (2 * ks + bseg_lo) ^ brows[np];
                    ldsm4(vf[np][0], vf[np][1], vf[np][2], vf[np][3],
                          Vb + browb[np] + seg * 16);
                }
                #pragma unroll
                for (int nt = 0; nt < 8; nt++)
                    mma_tf32(O[nt], pf, vf[nt >> 1] + (nt & 1) * 2);
            }
            __syncwarp();
        }
        __syncthreads();
    }

    const float i0 = 1.f / l0, i1 = 1.f / l1;
    #pragma unroll
    for (int nt = 0; nt < 8; nt++) {
        const int col = h * HDIM + nt * 8 + c0off;
        float2 v0 = make_float2(rna_tf32(O[nt][0] * i0), rna_tf32(O[nt][1] * i0));
        float2 v1 = make_float2(rna_tf32(O[nt][2] * i1), rna_tf32(O[nt][3] * i1));
        *(float2*)(out + (size_t)(b * Tlen + r0g) * HID + col) = v0;
        *(float2*)(out + (size_t)(b * Tlen + r1g) * HID + col) = v1;
    }
}

// ---------------------------------------------------------------------------
// Pre-passes
// ---------------------------------------------------------------------------
__global__ void round_tf32_kernel(const float* __restrict__ in,
                                  float* __restrict__ out, int n4)
{
    int i = blockIdx.x * blockDim.x + threadIdx.x;
    if (i < n4) {
        float4 v = ((const float4*)in)[i];
        v.x = rna_tf32(v.x); v.y = rna_tf32(v.y);
        v.z = rna_tf32(v.z); v.w = rna_tf32(v.w);
        ((float4*)out)[i] = v;
    }
}

__global__ void transpose_rna(const float* __restrict__ in,
                              float* __restrict__ out, int K, int N)
{
    __shared__ float tile[32][33];
    const int n0 = blockIdx.x * 32, k0 = blockIdx.y * 32;
    const int tx = threadIdx.x, ty = threadIdx.y;
    #pragma unroll
    for (int i = 0; i < 32; i += 8)
        tile[ty + i][tx] = in[(size_t)(k0 + ty + i) * N + n0 + tx];
    __syncthreads();
    #pragma unroll
    for (int i = 0; i < 32; i += 8)
        out[(size_t)(n0 + ty + i) * K + k0 + tx] = rna_tf32(tile[tx][ty + i]);
}

__global__ void vt_transpose(const float* __restrict__ qkv,
                             float* __restrict__ vtout)
{
    __shared__ float tile[32][33];
    const int t0 = blockIdx.x * 32, d0 = blockIdx.y * 32, bh = blockIdx.z;
    const int b = bh >> 4, h = bh & 15;
    const int tx = threadIdx.x, ty = threadIdx.y;
    const float* src = qkv + (size_t)b * Tlen * C3 + 2 * HID + h * HDIM;
    #pragma unroll
    for (int i = 0; i < 32; i += 8)
        tile[ty + i][tx] = src[(size_t)(t0 + ty + i) * C3 + d0 + tx];
    __syncthreads();
    float* dst = vtout + (size_t)bh * HDIM * Tlen;
    #pragma unroll
    for (int i = 0; i < 32; i += 8)
        dst[(size_t)(d0 + ty + i) * Tlen + t0 + tx] = tile[tx][ty + i];
}

// ---------------------------------------------------------------------------
// Launch
// ---------------------------------------------------------------------------
extern "C" void kernel_launch(void* const* d_in, const int* in_sizes, int n_in,
                              void* d_out, int out_size)
{
    const float* x     = (const float*)d_in[0];
    const float* Wqkv  = (const float*)d_in[1];
    const float* bqkv  = (const float*)d_in[2];
    const float* Wproj = (const float*)d_in[3];
    const float* bproj = (const float*)d_in[4];
    float* out = (float*)d_out;

    float *qkv_p, *att_p, *xr_p, *wtqkv_p, *wtproj_p, *vt_p;
    cudaGetSymbolAddress((void**)&qkv_p,    g_qkv);
    cudaGetSymbolAddress((void**)&att_p,    g_att);
    cudaGetSymbolAddress((void**)&xr_p,     g_xr);
    cudaGetSymbolAddress((void**)&wtqkv_p,  g_wtqkv);
    cudaGetSymbolAddress((void**)&wtproj_p, g_wtproj);
    cudaGetSymbolAddress((void**)&vt_p,     g_vt);

    cudaFuncSetAttribute(gemm_tf32mma,
                         cudaFuncAttributeMaxDynamicSharedMemorySize, G_SMEM);
    cudaFuncSetAttribute(flash_mma,
                         cudaFuncAttributeMaxDynamicSharedMemorySize, FA_SMEM);

    // 0) round x to tf32; transpose+round weights
    {
        int n4 = BT * HID / 4;
        round_tf32_kernel<<<(n4 + 255) / 256, 256>>>(x, xr_p, n4);
        dim3 blk(32, 8);
        transpose_rna<<<dim3(C3 / 32, HID / 32), blk>>>(Wqkv, wtqkv_p, HID, C3);
        transpose_rna<<<dim3(HID / 32, HID / 32), blk>>>(Wproj, wtproj_p, HID, HID);
    }
    // 1) qkv = xr @ Wqkv^T + b, rounded to tf32 for the attention mmas
    gemm_tf32mma<<<dim3(C3 / 128, BT / 128), 256, G_SMEM>>>(
        xr_p, wtqkv_p, bqkv, qkv_p, BT, C3, HID, 1);
    // 1b) V^T per (b,h)
    {
        dim3 blk(32, 8);
        vt_transpose<<<dim3(Tlen / 32, HDIM / 32, Bsz * HEADS), blk>>>(qkv_p, vt_p);
    }
    // 2) tensor-core causal flash attention
    flash_mma<<<dim3(Tlen / 128, Bsz * HEADS), 256, FA_SMEM>>>(qkv_p, vt_p, att_p);
    // 3) out = att @ Wproj^T + b (full fp32 epilogue)
    gemm_tf32mma<<<dim3(HID / 128, BT / 128), 256, G_SMEM>>>(
        att_p, wtproj_p, bproj, out, BT, HID, HID, 0);
}

// round 8
// speedup vs baseline: 7.8339x; 1.7162x over previous
#include <cuda_runtime.h>
#include <cuda_fp16.h>
#include <cstdint>

// ---------------------------------------------------------------------------
// Problem constants
// ---------------------------------------------------------------------------
namespace {
constexpr int Bsz   = 2;
constexpr int Tlen  = 2048;
constexpr int HID   = 1024;
constexpr int HEADS = 16;
constexpr int HDIM  = 64;
constexpr int BT    = Bsz * Tlen;   // 4096
constexpr int C3    = 3 * HID;      // 3072
}

// Scratch (__device__ globals per allocation-free rule) — all fp16 now
__device__ __half g_qkv[BT * C3];            // qkv projections (fp16)
__device__ __half g_att[BT * HID];           // attention out (fp16)
__device__ __half g_xh[BT * HID];            // x rounded to fp16
__device__ __half g_wtqkv[C3 * HID];         // W_qkv^T [3072,1024] K-major fp16
__device__ __half g_wtproj[HID * HID];       // W_proj^T [1024,1024] fp16
__device__ __half g_vt[Bsz * HEADS * HDIM * Tlen];  // V^T per (b,h): [64][2048]

// ---------------------------------------------------------------------------
// Helpers
// ---------------------------------------------------------------------------
__device__ __forceinline__ uint32_t smem_u32(const void* p) {
    uint32_t a;
    asm("{ .reg .u64 t; cvta.to.shared.u64 t, %1; cvt.u32.u64 %0, t; }"
        : "=r"(a) : "l"(p));
    return a;
}
// pack two f32 -> f16x2 (lo at low half)
__device__ __forceinline__ uint32_t f2h2(float lo, float hi) {
    uint32_t d;
    asm("cvt.rn.f16x2.f32 %0, %1, %2;" : "=r"(d) : "f"(hi), "f"(lo));
    return d;
}
__device__ __forceinline__ uint32_t hmul2_eighth(uint32_t x) {
    uint32_t d;
    asm("mul.rn.f16x2 %0, %1, %2;" : "=r"(d) : "r"(x), "r"(0x30003000u));
    return d;   // * 0.125 (exact)
}
__device__ __forceinline__ void ldsm4(uint32_t& r0, uint32_t& r1,
                                      uint32_t& r2, uint32_t& r3, uint32_t a) {
    asm volatile("ldmatrix.sync.aligned.m8n8.x4.shared.b16 {%0,%1,%2,%3}, [%4];"
                 : "=r"(r0), "=r"(r1), "=r"(r2), "=r"(r3) : "r"(a));
}
__device__ __forceinline__ void mma_f16(float* d, const uint32_t* a,
                                        const uint32_t* b) {
    asm volatile(
        "mma.sync.aligned.m16n8k16.row.col.f32.f16.f16.f32 "
        "{%0,%1,%2,%3}, {%4,%5,%6,%7}, {%8,%9}, {%0,%1,%2,%3};"
        : "+f"(d[0]), "+f"(d[1]), "+f"(d[2]), "+f"(d[3])
        : "r"(a[0]), "r"(a[1]), "r"(a[2]), "r"(a[3]), "r"(b[0]), "r"(b[1]));
}
__device__ __forceinline__ void cpasync16(uint32_t dst, const void* src) {
    asm volatile("cp.async.cg.shared.global [%0], [%1], 16;"
                 :: "r"(dst), "l"(src));
}

// Shared swizzled layout: 128B rows = 8 segs of 16B; conflict-free 8-row cycle.
#define G_OFF(row, seg) ((row) * 128 + ((((seg) ^ ((row) & 7))) * 16))

// ---------------------------------------------------------------------------
// FP16 mma.sync GEMM:  C[M,N] = A[M,K] @ Bt[N,K]^T + bias[N]
// A, Bt fp16 K-major. 128x128 tile, BK=64, 8 warps (warp 64x32, m16n8k16),
// 3-stage cp.async pipeline, one __syncthreads per K-iteration.
// Stage = A(16KB) + B(16KB) = 32KB; 3 stages = 96KB dynamic smem.
// out_half=1 -> C is fp16 (half2 stores); else f32.
// ---------------------------------------------------------------------------
constexpr int G_OPER  = 128 * 128;               // 16 KB (128 rows x 128B)
constexpr int G_STAGE = 2 * G_OPER;
constexpr int G_SMEM  = 3 * G_STAGE;

__global__ __launch_bounds__(256, 2) void gemm_f16mma(
    const __half* __restrict__ A, const __half* __restrict__ Bt,
    const float* __restrict__ bias, void* __restrict__ Cout,
    int M, int N, int K, int out_half)
{
    extern __shared__ __align__(128) char gsm[];
    const uint32_t s0 = smem_u32(gsm);

    const int tid = threadIdx.x, lane = tid & 31, wid = tid >> 5;
    const int bm = blockIdx.y * 128, bn = blockIdx.x * 128;
    const int warp_m = (wid & 1) * 64;
    const int warp_n = (wid >> 1) * 32;

    // cp.async: 4 segs per thread per operand per chunk (128 rows x 8 segs)
    uint32_t ld_off[4];
    const __half *srcA[4], *srcB[4];
    #pragma unroll
    for (int i = 0; i < 4; i++) {
        int idx = i * 256 + tid;
        int row = idx >> 3, seg = idx & 7;
        ld_off[i] = G_OFF(row, seg);
        srcA[i] = A + (size_t)(bm + row) * K + seg * 8;
        srcB[i] = Bt + (size_t)(bn + row) * K + seg * 8;
    }
    auto issue = [&](int chunk, int stage) {
        const uint32_t ab = s0 + stage * G_STAGE;
        const uint32_t bb = ab + G_OPER;
        const int koff = chunk * 64;
        #pragma unroll
        for (int i = 0; i < 4; i++) {
            cpasync16(ab + ld_off[i], srcA[i] + koff);
            cpasync16(bb + ld_off[i], srcB[i] + koff);
        }
        asm volatile("cp.async.commit_group;");
    };

    // ldmatrix lane address components (fp16 m16n8k16)
    uint32_t a_rowoff[4]; int a_sw[4];
    #pragma unroll
    for (int mt = 0; mt < 4; mt++) {
        int row = warp_m + mt * 16 + (lane & 7) + ((lane >> 3) & 1) * 8;
        a_rowoff[mt] = row * 128;
        a_sw[mt] = row & 7;
    }
    const int a_segbase = (lane >> 4);              // + 2*ks
    uint32_t b_rowoff[2]; int b_sw[2];
    #pragma unroll
    for (int np = 0; np < 2; np++) {
        int row = warp_n + np * 16 + ((lane >> 4) & 1) * 8 + (lane & 7);
        b_rowoff[np] = row * 128;
        b_sw[np] = row & 7;
    }
    const int b_segbase = ((lane >> 3) & 1);        // + 2*ks

    float acc[4][4][4];
    #pragma unroll
    for (int mt = 0; mt < 4; mt++)
        #pragma unroll
        for (int nt = 0; nt < 4; nt++)
            #pragma unroll
            for (int r = 0; r < 4; r++) acc[mt][nt][r] = 0.f;

    const int NIT = K >> 6;                          // 16 chunks for K=1024

    issue(0, 0);
    issue(1, 1);

    for (int c = 0; c < NIT; c++) {
        if (c < NIT - 1) {
            asm volatile("cp.async.wait_group 1;");
        } else {
            asm volatile("cp.async.wait_group 0;");
        }
        __syncthreads();
        if (c + 2 < NIT) issue(c + 2, (c + 2) % 3);

        const uint32_t ab = s0 + (c % 3) * G_STAGE;
        const uint32_t bb = ab + G_OPER;
        #pragma unroll
        for (int ks = 0; ks < 4; ks++) {            // 4 x k16 = BK 64
            uint32_t af[4][4], bf[2][4];
            #pragma unroll
            for (int mt = 0; mt < 4; mt++) {
                int seg = (2 * ks + a_segbase) ^ a_sw[mt];
                ldsm4(af[mt][0], af[mt][1], af[mt][2], af[mt][3],
                      ab + a_rowoff[mt] + seg * 16);
            }
            #pragma unroll
            for (int np = 0; np < 2; np++) {
                int seg = (2 * ks + b_segbase) ^ b_sw[np];
                ldsm4(bf[np][0], bf[np][1], bf[np][2], bf[np][3],
                      bb + b_rowoff[np] + seg * 16);
            }
            #pragma unroll
            for (int mt = 0; mt < 4; mt++)
                #pragma unroll
                for (int nt = 0; nt < 4; nt++)
                    mma_f16(acc[mt][nt], af[mt], bf[nt >> 1] + (nt & 1) * 2);
        }
    }

    const int er = lane >> 2, ec = (lane & 3) * 2;
    #pragma unroll
    for (int mt = 0; mt < 4; mt++) {
        const int row0 = bm + warp_m + mt * 16 + er;
        #pragma unroll
        for (int nt = 0; nt < 4; nt++) {
            const int col = bn + warp_n + nt * 8 + ec;
            const float b0 = bias[col], b1 = bias[col + 1];
            float c0 = acc[mt][nt][0] + b0, c1 = acc[mt][nt][1] + b1;
            float c2 = acc[mt][nt][2] + b0, c3 = acc[mt][nt][3] + b1;
            if (out_half) {
                __half* C = (__half*)Cout;
                *(uint32_t*)(C + (size_t)row0 * N + col)       = f2h2(c0, c1);
                *(uint32_t*)(C + (size_t)(row0 + 8) * N + col) = f2h2(c2, c3);
            } else {
                float* C = (float*)Cout;
                *(float2*)(C + (size_t)row0 * N + col)       = make_float2(c0, c1);
                *(float2*)(C + (size_t)(row0 + 8) * N + col) = make_float2(c2, c3);
            }
        }
    }
}

// ---------------------------------------------------------------------------
// Tensor-core causal flash attention, fp16 mma (m16n8k16), fp32 softmax/acc.
// Block: one (b,h) x 128 q-rows, 8 warps x m16. Key tiles Bc=64, double-
// buffered. Q buffer (16KB) reused as warp-private P staging.
// ---------------------------------------------------------------------------
constexpr int FA_SMEM = 16384 + 2 * 8192 + 2 * 8192;   // 48KB

__global__ __launch_bounds__(256) void flash_mma(
    const __half* __restrict__ qkv, const __half* __restrict__ vt,
    __half* __restrict__ out)
{
    extern __shared__ char fsm[];
    const uint32_t sQ = smem_u32(fsm);         // 16KB, later P staging
    const uint32_t sK = sQ + 16384;            // 2 x 8KB
    const uint32_t sV = sQ + 32768;            // 2 x 8KB
    const int tid = threadIdx.x, lane = tid & 31, w = tid >> 5;
    const int qb = gridDim.x - 1 - blockIdx.x;
    const int bh = blockIdx.y;
    const int b = bh >> 4, h = bh & 15;

    const __half* qbase  = qkv + (size_t)b * Tlen * C3 + h * HDIM;
    const __half* kbase  = qbase + HID;
    const __half* vtbase = vt + (size_t)bh * HDIM * Tlen;

    auto loadKV = [&](int kb, int s) {
        const uint32_t so = s * 8192;
        #pragma unroll
        for (int i = 0; i < 2; i++) {          // 64 rows x 8 segs = 512
            int idx = i * 256 + tid;
            int row = idx >> 3, seg = idx & 7;
            uint32_t off = G_OFF(row, seg);
            cpasync16(sK + so + off,
                      kbase + (size_t)(kb * 64 + row) * C3 + seg * 8);
            cpasync16(sV + so + off,
                      vtbase + (size_t)row * Tlen + kb * 64 + seg * 8);
        }
    };

    #pragma unroll
    for (int i = 0; i < 4; i++) {              // Q: 128 rows x 8 segs
        int idx = i * 256 + tid;
        int row = idx >> 3, seg = idx & 7;
        cpasync16(sQ + G_OFF(row, seg),
                  qbase + (size_t)(qb * 128 + row) * C3 + seg * 8);
    }
    loadKV(0, 0);
    asm volatile("cp.async.commit_group;");
    asm volatile("cp.async.wait_group 0;");
    __syncthreads();

    // A-frag geometry (Q and P share it; rows warp-private)
    const int frow = w * 16 + (lane & 7) + ((lane >> 3) & 1) * 8;
    const uint32_t frow_b = frow * 128;
    const int frow_s = frow & 7;
    const int fseg_hi = lane >> 4;             // + 2*ks

    uint32_t qf[4][4];
    #pragma unroll
    for (int ks = 0; ks < 4; ks++) {
        ldsm4(qf[ks][0], qf[ks][1], qf[ks][2], qf[ks][3],
              sQ + frow_b + (((2 * ks + fseg_hi) ^ frow_s) * 16));
        #pragma unroll
        for (int r = 0; r < 4; r++)            // fold 1/sqrt(64)=0.125 exact
            qf[ks][r] = hmul2_eighth(qf[ks][r]);
    }

    // B-frag geometry (K and V^T share it)
    uint32_t browb[4]; int brows[4];
    #pragma unroll
    for (int np = 0; np < 4; np++) {
        int row = np * 16 + ((lane >> 4) & 1) * 8 + (lane & 7);
        browb[np] = row * 128;
        brows[np] = row & 7;
    }
    const int bseg_lo = (lane >> 3) & 1;       // + 2*ks

    float O[8][4];
    #pragma unroll
    for (int nt = 0; nt < 8; nt++)
        #pragma unroll
        for (int r = 0; r < 4; r++) O[nt][r] = 0.f;
    float m0 = -1e30f, m1 = -1e30f, l0 = 0.f, l1 = 0.f;

    const int rw = qb * 128 + w * 16;
    const int nkb = 2 * qb + 2;
    const int c0off = 2 * (lane & 3);
    const int r0g = rw + (lane >> 2);
    const int r1g = r0g + 8;
    const int prow0 = w * 16 + (lane >> 2);
    const int prow1 = prow0 + 8;

    for (int kb = 0; kb < nkb; kb++) {
        const int s = kb & 1;
        if (kb + 1 < nkb) {
            loadKV(kb + 1, 1 - s);
            asm volatile("cp.async.commit_group;");
            asm volatile("cp.async.wait_group 1;");
        } else {
            asm volatile("cp.async.wait_group 0;");
        }
        __syncthreads();

        if (kb * 64 <= rw + 15) {              // warp-uniform
            const uint32_t Kb = sK + s * 8192, Vb = sV + s * 8192;
            float S[8][4];
            #pragma unroll
            for (int nt = 0; nt < 8; nt++)
                #pragma unroll
                for (int r = 0; r < 4; r++) S[nt][r] = 0.f;

            // S = (Q/8) @ K^T
            #pragma unroll
            for (int ks = 0; ks < 4; ks++) {
                uint32_t kf[4][4];
                #pragma unroll
                for (int np = 0; np < 4; np++) {
                    int seg = (2 * ks + bseg_lo) ^ brows[np];
                    ldsm4(kf[np][0], kf[np][1], kf[np][2], kf[np][3],
                          Kb + browb[np] + seg * 16);
                }
                #pragma unroll
                for (int nt = 0; nt < 8; nt++)
                    mma_f16(S[nt], qf[ks], kf[nt >> 1] + (nt & 1) * 2);
            }

            // causal mask (diagonal tiles only)
            if (kb * 64 + 63 > rw) {
                #pragma unroll
                for (int nt = 0; nt < 8; nt++) {
                    int c = kb * 64 + nt * 8 + c0off;
                    if (c     > r0g) S[nt][0] = -1e30f;
                    if (c + 1 > r0g) S[nt][1] = -1e30f;
                    if (c     > r1g) S[nt][2] = -1e30f;
                    if (c + 1 > r1g) S[nt][3] = -1e30f;
                }
            }

            // online softmax
            float mx0 = -1e30f, mx1 = -1e30f;
            #pragma unroll
            for (int nt = 0; nt < 8; nt++) {
                mx0 = fmaxf(mx0, fmaxf(S[nt][0], S[nt][1]));
                mx1 = fmaxf(mx1, fmaxf(S[nt][2], S[nt][3]));
            }
            mx0 = fmaxf(mx0, __shfl_xor_sync(0xffffffffu, mx0, 1));
            mx0 = fmaxf(mx0, __shfl_xor_sync(0xffffffffu, mx0, 2));
            mx1 = fmaxf(mx1, __shfl_xor_sync(0xffffffffu, mx1, 1));
            mx1 = fmaxf(mx1, __shfl_xor_sync(0xffffffffu, mx1, 2));
            const float mn0 = fmaxf(m0, mx0), mn1 = fmaxf(m1, mx1);
            const float cr0 = __expf(m0 - mn0), cr1 = __expf(m1 - mn1);
            float sum0 = 0.f, sum1 = 0.f;
            #pragma unroll
            for (int nt = 0; nt < 8; nt++) {
                S[nt][0] = __expf(S[nt][0] - mn0);
                S[nt][1] = __expf(S[nt][1] - mn0);
                S[nt][2] = __expf(S[nt][2] - mn1);
                S[nt][3] = __expf(S[nt][3] - mn1);
                sum0 += S[nt][0] + S[nt][1];
                sum1 += S[nt][2] + S[nt][3];
            }
            sum0 += __shfl_xor_sync(0xffffffffu, sum0, 1);
            sum0 += __shfl_xor_sync(0xffffffffu, sum0, 2);
            sum1 += __shfl_xor_sync(0xffffffffu, sum1, 1);
            sum1 += __shfl_xor_sync(0xffffffffu, sum1, 2);
            l0 = l0 * cr0 + sum0; m0 = mn0;
            l1 = l1 * cr1 + sum1; m1 = mn1;
            #pragma unroll
            for (int nt = 0; nt < 8; nt++) {
                O[nt][0] *= cr0; O[nt][1] *= cr0;
                O[nt][2] *= cr1; O[nt][3] *= cr1;
            }

            // P (fp16) -> warp-private rows of the Q buffer
            #pragma unroll
            for (int nt = 0; nt < 8; nt++) {
                uint32_t inseg = 4 * (lane & 3);
                uint32_t ad0 = sQ + prow0 * 128 +
                               ((nt ^ (prow0 & 7)) * 16) + inseg;
                uint32_t ad1 = sQ + prow1 * 128 +
                               ((nt ^ (prow1 & 7)) * 16) + inseg;
                uint32_t p01 = f2h2(S[nt][0], S[nt][1]);
                uint32_t p23 = f2h2(S[nt][2], S[nt][3]);
                asm volatile("st.shared.b32 [%0], %1;" :: "r"(ad0), "r"(p01)
                             : "memory");
                asm volatile("st.shared.b32 [%0], %1;" :: "r"(ad1), "r"(p23)
                             : "memory");
            }
            __syncwarp();

            // O += P @ V  (V^T tile: rows=hdim, cols=keys)
            #pragma unroll
            for (int ks = 0; ks < 4; ks++) {
                uint32_t pf[4];
                ldsm4(pf[0], pf[1], pf[2], pf[3],
                      sQ + frow_b + (((2 * ks + fseg_hi) ^ frow_s) * 16));
                uint32_t vf[4][4];
                #pragma unroll
                for (int np = 0; np < 4; np++) {
                    int seg = (2 * ks + bseg_lo) ^ brows[np];
                    ldsm4(vf[np][0], vf[np][1], vf[np][2], vf[np][3],
                          Vb + browb[np] + seg * 16);
                }
                #pragma unroll
                for (int nt = 0; nt < 8; nt++)
                    mma_f16(O[nt], pf, vf[nt >> 1] + (nt & 1) * 2);
            }
            __syncwarp();
        }
        __syncthreads();
    }

    const float i0 = 1.f / l0, i1 = 1.f / l1;
    #pragma unroll
    for (int nt = 0; nt < 8; nt++) {
        const int col = h * HDIM + nt * 8 + c0off;
        *(uint32_t*)(out + (size_t)(b * Tlen + r0g) * HID + col) =
            f2h2(O[nt][0] * i0, O[nt][1] * i0);
        *(uint32_t*)(out + (size_t)(b * Tlen + r1g) * HID + col) =
            f2h2(O[nt][2] * i1, O[nt][3] * i1);
    }
}

// ---------------------------------------------------------------------------
// Pre-passes
// ---------------------------------------------------------------------------
__global__ void round_h_kernel(const float* __restrict__ in,
                               __half* __restrict__ out, int n4)
{
    int i = blockIdx.x * blockDim.x + threadIdx.x;
    if (i < n4) {
        float4 v = ((const float4*)in)[i];
        uint2 o;
        o.x = f2h2(v.x, v.y);
        o.y = f2h2(v.z, v.w);
        ((uint2*)out)[i] = o;
    }
}

// W[K][N] f32 -> Wt[N][K] fp16
__global__ void transpose_h(const float* __restrict__ in,
                            __half* __restrict__ out, int K, int N)
{
    __shared__ float tile[32][33];
    const int n0 = blockIdx.x * 32, k0 = blockIdx.y * 32;
    const int tx = threadIdx.x, ty = threadIdx.y;
    #pragma unroll
    for (int i = 0; i < 32; i += 8)
        tile[ty + i][tx] = in[(size_t)(k0 + ty + i) * N + n0 + tx];
    __syncthreads();
    #pragma unroll
    for (int i = 0; i < 32; i += 8)
        out[(size_t)(n0 + ty + i) * K + k0 + tx] = __float2half(tile[tx][ty + i]);
}

// V^T per (b,h): qkv fp16 V slice [tok][64] -> vt [bh][64][Tlen] fp16
__global__ void vt_transpose(const __half* __restrict__ qkv,
                             __half* __restrict__ vtout)
{
    __shared__ float tile[32][33];
    const int t0 = blockIdx.x * 32, d0 = blockIdx.y * 32, bh = blockIdx.z;
    const int b = bh >> 4, h = bh & 15;
    const int tx = threadIdx.x, ty = threadIdx.y;
    const __half* src = qkv + (size_t)b * Tlen * C3 + 2 * HID + h * HDIM;
    #pragma unroll
    for (int i = 0; i < 32; i += 8)
        tile[ty + i][tx] = __half2float(src[(size_t)(t0 + ty + i) * C3 + d0 + tx]);
    __syncthreads();
    __half* dst = vtout + (size_t)bh * HDIM * Tlen;
    #pragma unroll
    for (int i = 0; i < 32; i += 8)
        dst[(size_t)(d0 + ty + i) * Tlen + t0 + tx] = __float2half(tile[tx][ty + i]);
}

// ---------------------------------------------------------------------------
// Launch
// ---------------------------------------------------------------------------
extern "C" void kernel_launch(void* const* d_in, const int* in_sizes, int n_in,
                              void* d_out, int out_size)
{
    const float* x     = (const float*)d_in[0];
    const float* Wqkv  = (const float*)d_in[1];
    const float* bqkv  = (const float*)d_in[2];
    const float* Wproj = (const float*)d_in[3];
    const float* bproj = (const float*)d_in[4];
    float* out = (float*)d_out;

    __half *qkv_p, *att_p, *xh_p, *wtqkv_p, *wtproj_p, *vt_p;
    cudaGetSymbolAddress((void**)&qkv_p,    g_qkv);
    cudaGetSymbolAddress((void**)&att_p,    g_att);
    cudaGetSymbolAddress((void**)&xh_p,     g_xh);
    cudaGetSymbolAddress((void**)&wtqkv_p,  g_wtqkv);
    cudaGetSymbolAddress((void**)&wtproj_p, g_wtproj);
    cudaGetSymbolAddress((void**)&vt_p,     g_vt);

    cudaFuncSetAttribute(gemm_f16mma,
                         cudaFuncAttributeMaxDynamicSharedMemorySize, G_SMEM);
    cudaFuncSetAttribute(flash_mma,
                         cudaFuncAttributeMaxDynamicSharedMemorySize, FA_SMEM);

    // 0) round x to fp16; transpose+round weights
    {
        int n4 = BT * HID / 4;
        round_h_kernel<<<(n4 + 255) / 256, 256>>>(x, xh_p, n4);
        dim3 blk(32, 8);
        transpose_h<<<dim3(C3 / 32, HID / 32), blk>>>(Wqkv, wtqkv_p, HID, C3);
        transpose_h<<<dim3(HID / 32, HID / 32), blk>>>(Wproj, wtproj_p, HID, HID);
    }
    // 1) qkv = xh @ Wqkv^T + b  -> fp16
    gemm_f16mma<<<dim3(C3 / 128, BT / 128), 256, G_SMEM>>>(
        xh_p, wtqkv_p, bqkv, qkv_p, BT, C3, HID, 1);
    // 1b) V^T per (b,h)
    {
        dim3 blk(32, 8);
        vt_transpose<<<dim3(Tlen / 32, HDIM / 32, Bsz * HEADS), blk>>>(qkv_p, vt_p);
    }
    // 2) tensor-core causal flash attention -> fp16
    flash_mma<<<dim3(Tlen / 128, Bsz * HEADS), 256, FA_SMEM>>>(qkv_p, vt_p, att_p);
    // 3) out = att @ Wproj^T + b -> f32
    gemm_f16mma<<<dim3(HID / 128, BT / 128), 256, G_SMEM>>>(
        att_p, wtproj_p, bproj, out, BT, HID, HID, 0);
}

// round 9
// speedup vs baseline: 8.3197x; 1.0620x over previous
#include <cuda_runtime.h>
#include <cuda_fp16.h>
#include <cstdint>

// ---------------------------------------------------------------------------
// Problem constants
// ---------------------------------------------------------------------------
namespace {
constexpr int Bsz   = 2;
constexpr int Tlen  = 2048;
constexpr int HID   = 1024;
constexpr int HEADS = 16;
constexpr int HDIM  = 64;
constexpr int BT    = Bsz * Tlen;   // 4096
constexpr int C3    = 3 * HID;      // 3072
}

// Scratch (__device__ globals per allocation-free rule)
__device__ __half g_qkv[BT * C3];            // qkv projections (fp16)
__device__ __half g_att[BT * HID];           // attention out (fp16)
__device__ __half g_xh[BT * HID];            // x rounded to fp16
__device__ __half g_wtqkv[C3 * HID];         // W_qkv^T [3072,1024] K-major fp16
__device__ __half g_wtproj[HID * HID];       // W_proj^T [1024,1024] fp16

// ---------------------------------------------------------------------------
// Helpers
// ---------------------------------------------------------------------------
__device__ __forceinline__ uint32_t smem_u32(const void* p) {
    uint32_t a;
    asm("{ .reg .u64 t; cvta.to.shared.u64 t, %1; cvt.u32.u64 %0, t; }"
        : "=r"(a) : "l"(p));
    return a;
}
__device__ __forceinline__ uint32_t f2h2(float lo, float hi) {
    uint32_t d;
    asm("cvt.rn.f16x2.f32 %0, %1, %2;" : "=r"(d) : "f"(hi), "f"(lo));
    return d;
}
__device__ __forceinline__ uint32_t hmul2_eighth(uint32_t x) {
    uint32_t d;
    asm("mul.rn.f16x2 %0, %1, %2;" : "=r"(d) : "r"(x), "r"(0x30003000u));
    return d;   // * 0.125 (exact)
}
__device__ __forceinline__ void ldsm4(uint32_t& r0, uint32_t& r1,
                                      uint32_t& r2, uint32_t& r3, uint32_t a) {
    asm volatile("ldmatrix.sync.aligned.m8n8.x4.shared.b16 {%0,%1,%2,%3}, [%4];"
                 : "=r"(r0), "=r"(r1), "=r"(r2), "=r"(r3) : "r"(a));
}
__device__ __forceinline__ void ldsm4t(uint32_t& r0, uint32_t& r1,
                                       uint32_t& r2, uint32_t& r3, uint32_t a) {
    asm volatile(
        "ldmatrix.sync.aligned.m8n8.x4.trans.shared.b16 {%0,%1,%2,%3}, [%4];"
        : "=r"(r0), "=r"(r1), "=r"(r2), "=r"(r3) : "r"(a));
}
__device__ __forceinline__ void mma_f16(float* d, const uint32_t* a,
                                        const uint32_t* b) {
    asm volatile(
        "mma.sync.aligned.m16n8k16.row.col.f32.f16.f16.f32 "
        "{%0,%1,%2,%3}, {%4,%5,%6,%7}, {%8,%9}, {%0,%1,%2,%3};"
        : "+f"(d[0]), "+f"(d[1]), "+f"(d[2]), "+f"(d[3])
        : "r"(a[0]), "r"(a[1]), "r"(a[2]), "r"(a[3]), "r"(b[0]), "r"(b[1]));
}
__device__ __forceinline__ void cpasync16(uint32_t dst, const void* src) {
    asm volatile("cp.async.cg.shared.global [%0], [%1], 16;"
                 :: "r"(dst), "l"(src));
}

// Shared swizzled layout: 128B rows = 8 segs of 16B; conflict-free 8-row cycle.
#define G_OFF(row, seg) ((row) * 128 + ((((seg) ^ ((row) & 7))) * 16))

// ---------------------------------------------------------------------------
// FP16 mma.sync GEMM (verified R8):  C[M,N] = A[M,K] @ Bt[N,K]^T + bias[N]
// 128x128 tile, BK=64, 8 warps (warp 64x32, m16n8k16), 3-stage cp.async
// pipeline, one __syncthreads per K-iteration. out_half selects fp16/f32 C.
// ---------------------------------------------------------------------------
constexpr int G_OPER  = 128 * 128;               // 16 KB
constexpr int G_STAGE = 2 * G_OPER;
constexpr int G_SMEM  = 3 * G_STAGE;             // 96 KB

__global__ __launch_bounds__(256, 2) void gemm_f16mma(
    const __half* __restrict__ A, const __half* __restrict__ Bt,
    const float* __restrict__ bias, void* __restrict__ Cout,
    int M, int N, int K, int out_half)
{
    extern __shared__ __align__(128) char gsm[];
    const uint32_t s0 = smem_u32(gsm);

    const int tid = threadIdx.x, lane = tid & 31, wid = tid >> 5;
    const int bm = blockIdx.y * 128, bn = blockIdx.x * 128;
    const int warp_m = (wid & 1) * 64;
    const int warp_n = (wid >> 1) * 32;

    uint32_t ld_off[4];
    const __half *srcA[4], *srcB[4];
    #pragma unroll
    for (int i = 0; i < 4; i++) {
        int idx = i * 256 + tid;
        int row = idx >> 3, seg = idx & 7;
        ld_off[i] = G_OFF(row, seg);
        srcA[i] = A + (size_t)(bm + row) * K + seg * 8;
        srcB[i] = Bt + (size_t)(bn + row) * K + seg * 8;
    }
    auto issue = [&](int chunk, int stage) {
        const uint32_t ab = s0 + stage * G_STAGE;
        const uint32_t bb = ab + G_OPER;
        const int koff = chunk * 64;
        #pragma unroll
        for (int i = 0; i < 4; i++) {
            cpasync16(ab + ld_off[i], srcA[i] + koff);
            cpasync16(bb + ld_off[i], srcB[i] + koff);
        }
        asm volatile("cp.async.commit_group;");
    };

    uint32_t a_rowoff[4]; int a_sw[4];
    #pragma unroll
    for (int mt = 0; mt < 4; mt++) {
        int row = warp_m + mt * 16 + (lane & 7) + ((lane >> 3) & 1) * 8;
        a_rowoff[mt] = row * 128;
        a_sw[mt] = row & 7;
    }
    const int a_segbase = (lane >> 4);
    uint32_t b_rowoff[2]; int b_sw[2];
    #pragma unroll
    for (int np = 0; np < 2; np++) {
        int row = warp_n + np * 16 + ((lane >> 4) & 1) * 8 + (lane & 7);
        b_rowoff[np] = row * 128;
        b_sw[np] = row & 7;
    }
    const int b_segbase = ((lane >> 3) & 1);

    float acc[4][4][4];
    #pragma unroll
    for (int mt = 0; mt < 4; mt++)
        #pragma unroll
        for (int nt = 0; nt < 4; nt++)
            #pragma unroll
            for (int r = 0; r < 4; r++) acc[mt][nt][r] = 0.f;

    const int NIT = K >> 6;

    issue(0, 0);
    issue(1, 1);

    for (int c = 0; c < NIT; c++) {
        if (c < NIT - 1) {
            asm volatile("cp.async.wait_group 1;");
        } else {
            asm volatile("cp.async.wait_group 0;");
        }
        __syncthreads();
        if (c + 2 < NIT) issue(c + 2, (c + 2) % 3);

        const uint32_t ab = s0 + (c % 3) * G_STAGE;
        const uint32_t bb = ab + G_OPER;
        #pragma unroll
        for (int ks = 0; ks < 4; ks++) {
            uint32_t af[4][4], bf[2][4];
            #pragma unroll
            for (int mt = 0; mt < 4; mt++) {
                int seg = (2 * ks + a_segbase) ^ a_sw[mt];
                ldsm4(af[mt][0], af[mt][1], af[mt][2], af[mt][3],
                      ab + a_rowoff[mt] + seg * 16);
            }
            #pragma unroll
            for (int np = 0; np < 2; np++) {
                int seg = (2 * ks + b_segbase) ^ b_sw[np];
                ldsm4(bf[np][0], bf[np][1], bf[np][2], bf[np][3],
                      bb + b_rowoff[np] + seg * 16);
            }
            #pragma unroll
            for (int mt = 0; mt < 4; mt++)
                #pragma unroll
                for (int nt = 0; nt < 4; nt++)
                    mma_f16(acc[mt][nt], af[mt], bf[nt >> 1] + (nt & 1) * 2);
        }
    }

    const int er = lane >> 2, ec = (lane & 3) * 2;
    #pragma unroll
    for (int mt = 0; mt < 4; mt++) {
        const int row0 = bm + warp_m + mt * 16 + er;
        #pragma unroll
        for (int nt = 0; nt < 4; nt++) {
            const int col = bn + warp_n + nt * 8 + ec;
            const float b0 = bias[col], b1 = bias[col + 1];
            float c0 = acc[mt][nt][0] + b0, c1 = acc[mt][nt][1] + b1;
            float c2 = acc[mt][nt][2] + b0, c3 = acc[mt][nt][3] + b1;
            if (out_half) {
                __half* C = (__half*)Cout;
                *(uint32_t*)(C + (size_t)row0 * N + col)       = f2h2(c0, c1);
                *(uint32_t*)(C + (size_t)(row0 + 8) * N + col) = f2h2(c2, c3);
            } else {
                float* C = (float*)Cout;
                *(float2*)(C + (size_t)row0 * N + col)       = make_float2(c0, c1);
                *(float2*)(C + (size_t)(row0 + 8) * N + col) = make_float2(c2, c3);
            }
        }
    }
}

// ---------------------------------------------------------------------------
// Tensor-core causal flash attention, fp16 mma, fp32 softmax/accum.
// V is loaded K-major straight from qkv (same as K); the PV mma gets its
// V^T B-fragments via ldmatrix.trans — no V pre-transpose kernel needed.
// ---------------------------------------------------------------------------
constexpr int FA_SMEM = 16384 + 2 * 8192 + 2 * 8192;   // 48KB

__global__ __launch_bounds__(256) void flash_mma(
    const __half* __restrict__ qkv, __half* __restrict__ out)
{
    extern __shared__ char fsm[];
    const uint32_t sQ = smem_u32(fsm);         // 16KB, later P staging
    const uint32_t sK = sQ + 16384;            // 2 x 8KB
    const uint32_t sV = sQ + 32768;            // 2 x 8KB
    const int tid = threadIdx.x, lane = tid & 31, w = tid >> 5;
    const int qb = gridDim.x - 1 - blockIdx.x;
    const int bh = blockIdx.y;
    const int b = bh >> 4, h = bh & 15;

    const __half* qbase = qkv + (size_t)b * Tlen * C3 + h * HDIM;
    const __half* kbase = qbase + HID;
    const __half* vbase = qbase + 2 * HID;

    auto loadKV = [&](int kb, int s) {
        const uint32_t so = s * 8192;
        #pragma unroll
        for (int i = 0; i < 2; i++) {          // 64 rows x 8 segs = 512
            int idx = i * 256 + tid;
            int row = idx >> 3, seg = idx & 7;
            uint32_t off = G_OFF(row, seg);
            const size_t g = (size_t)(kb * 64 + row) * C3 + seg * 8;
            cpasync16(sK + so + off, kbase + g);
            cpasync16(sV + so + off, vbase + g);
        }
    };

    #pragma unroll
    for (int i = 0; i < 4; i++) {              // Q: 128 rows x 8 segs
        int idx = i * 256 + tid;
        int row = idx >> 3, seg = idx & 7;
        cpasync16(sQ + G_OFF(row, seg),
                  qbase + (size_t)(qb * 128 + row) * C3 + seg * 8);
    }
    loadKV(0, 0);
    asm volatile("cp.async.commit_group;");
    asm volatile("cp.async.wait_group 0;");
    __syncthreads();

    // A-frag geometry (Q and P share it; rows warp-private)
    const int frow = w * 16 + (lane & 7) + ((lane >> 3) & 1) * 8;
    const uint32_t frow_b = frow * 128;
    const int frow_s = frow & 7;
    const int fseg_hi = lane >> 4;             // + 2*ks

    uint32_t qf[4][4];
    #pragma unroll
    for (int ks = 0; ks < 4; ks++) {
        ldsm4(qf[ks][0], qf[ks][1], qf[ks][2], qf[ks][3],
              sQ + frow_b + (((2 * ks + fseg_hi) ^ frow_s) * 16));
        #pragma unroll
        for (int r = 0; r < 4; r++)
            qf[ks][r] = hmul2_eighth(qf[ks][r]);
    }

    // K B-frag geometry (non-trans)
    uint32_t browb[4]; int brows[4];
    #pragma unroll
    for (int np = 0; np < 4; np++) {
        int row = np * 16 + ((lane >> 4) & 1) * 8 + (lane & 7);
        browb[np] = row * 128;
        brows[np] = row & 7;
    }
    const int bseg_lo = (lane >> 3) & 1;

    // V B-frag geometry (trans, from K-major V tile)
    const int vrow_base = ((lane >> 3) & 1) * 8 + (lane & 7);
    const int vseg_base = (lane >> 4) & 1;

    float O[8][4];
    #pragma unroll
    for (int nt = 0; nt < 8; nt++)
        #pragma unroll
        for (int r = 0; r < 4; r++) O[nt][r] = 0.f;
    float m0 = -1e30f, m1 = -1e30f, l0 = 0.f, l1 = 0.f;

    const int rw = qb * 128 + w * 16;
    const int nkb = 2 * qb + 2;
    const int c0off = 2 * (lane & 3);
    const int r0g = rw + (lane >> 2);
    const int r1g = r0g + 8;
    const int prow0 = w * 16 + (lane >> 2);
    const int prow1 = prow0 + 8;

    for (int kb = 0; kb < nkb; kb++) {
        const int s = kb & 1;
        if (kb + 1 < nkb) {
            loadKV(kb + 1, 1 - s);
            asm volatile("cp.async.commit_group;");
            asm volatile("cp.async.wait_group 1;");
        } else {
            asm volatile("cp.async.wait_group 0;");
        }
        __syncthreads();

        if (kb * 64 <= rw + 15) {              // warp-uniform
            const uint32_t Kb = sK + s * 8192, Vb = sV + s * 8192;
            float S[8][4];
            #pragma unroll
            for (int nt = 0; nt < 8; nt++)
                #pragma unroll
                for (int r = 0; r < 4; r++) S[nt][r] = 0.f;

            // S = (Q/8) @ K^T
            #pragma unroll
            for (int ks = 0; ks < 4; ks++) {
                uint32_t kf[4][4];
                #pragma unroll
                for (int np = 0; np < 4; np++) {
                    int seg = (2 * ks + bseg_lo) ^ brows[np];
                    ldsm4(kf[np][0], kf[np][1], kf[np][2], kf[np][3],
                          Kb + browb[np] + seg * 16);
                }
                #pragma unroll
                for (int nt = 0; nt < 8; nt++)
                    mma_f16(S[nt], qf[ks], kf[nt >> 1] + (nt & 1) * 2);
            }

            // causal mask (diagonal tiles only)
            if (kb * 64 + 63 > rw) {
                #pragma unroll
                for (int nt = 0; nt < 8; nt++) {
                    int c = kb * 64 + nt * 8 + c0off;
                    if (c     > r0g) S[nt][0] = -1e30f;
                    if (c + 1 > r0g) S[nt][1] = -1e30f;
                    if (c     > r1g) S[nt][2] = -1e30f;
                    if (c + 1 > r1g) S[nt][3] = -1e30f;
                }
            }

            // online softmax
            float mx0 = -1e30f, mx1 = -1e30f;
            #pragma unroll
            for (int nt = 0; nt < 8; nt++) {
                mx0 = fmaxf(mx0, fmaxf(S[nt][0], S[nt][1]));
                mx1 = fmaxf(mx1, fmaxf(S[nt][2], S[nt][3]));
            }
            mx0 = fmaxf(mx0, __shfl_xor_sync(0xffffffffu, mx0, 1));
            mx0 = fmaxf(mx0, __shfl_xor_sync(0xffffffffu, mx0, 2));
            mx1 = fmaxf(mx1, __shfl_xor_sync(0xffffffffu, mx1, 1));
            mx1 = fmaxf(mx1, __shfl_xor_sync(0xffffffffu, mx1, 2));
            const float mn0 = fmaxf(m0, mx0), mn1 = fmaxf(m1, mx1);
            const float cr0 = __expf(m0 - mn0), cr1 = __expf(m1 - mn1);
            float sum0 = 0.f, sum1 = 0.f;
            #pragma unroll
            for (int nt = 0; nt < 8; nt++) {
                S[nt][0] = __expf(S[nt][0] - mn0);
                S[nt][1] = __expf(S[nt][1] - mn0);
                S[nt][2] = __expf(S[nt][2] - mn1);
                S[nt][3] = __expf(S[nt][3] - mn1);
                sum0 += S[nt][0] + S[nt][1];
                sum1 += S[nt][2] + S[nt][3];
            }
            sum0 += __shfl_xor_sync(0xffffffffu, sum0, 1);
            sum0 += __shfl_xor_sync(0xffffffffu, sum0, 2);
            sum1 += __shfl_xor_sync(0xffffffffu, sum1, 1);
            sum1 += __shfl_xor_sync(0xffffffffu, sum1, 2);
            l0 = l0 * cr0 + sum0; m0 = mn0;
            l1 = l1 * cr1 + sum1; m1 = mn1;
            #pragma unroll
            for (int nt = 0; nt < 8; nt++) {
                O[nt][0] *= cr0; O[nt][1] *= cr0;
                O[nt][2] *= cr1; O[nt][3] *= cr1;
            }

            // P (fp16) -> warp-private rows of the Q buffer
            #pragma unroll
            for (int nt = 0; nt < 8; nt++) {
                uint32_t inseg = 4 * (lane & 3);
                uint32_t ad0 = sQ + prow0 * 128 +
                               ((nt ^ (prow0 & 7)) * 16) + inseg;
                uint32_t ad1 = sQ + prow1 * 128 +
                               ((nt ^ (prow1 & 7)) * 16) + inseg;
                uint32_t p01 = f2h2(S[nt][0], S[nt][1]);
                uint32_t p23 = f2h2(S[nt][2], S[nt][3]);
                asm volatile("st.shared.b32 [%0], %1;" :: "r"(ad0), "r"(p01)
                             : "memory");
                asm volatile("st.shared.b32 [%0], %1;" :: "r"(ad1), "r"(p23)
                             : "memory");
            }
            __syncwarp();

            // O += P @ V  (V tile K-major; B-frags via ldsm.trans)
            #pragma unroll
            for (int ks = 0; ks < 4; ks++) {
                uint32_t pf[4];
                ldsm4(pf[0], pf[1], pf[2], pf[3],
                      sQ + frow_b + (((2 * ks + fseg_hi) ^ frow_s) * 16));
                const int vrow = 16 * ks + vrow_base;
                const uint32_t vrb = Vb + vrow * 128;
                const int vsw = vrow & 7;
                uint32_t vf[4][4];
                #pragma unroll
                for (int np = 0; np < 4; np++) {
                    int seg = (2 * np + vseg_base) ^ vsw;
                    ldsm4t(vf[np][0], vf[np][1], vf[np][2], vf[np][3],
                           vrb + seg * 16);
                }
                #pragma unroll
                for (int nt = 0; nt < 8; nt++)
                    mma_f16(O[nt], pf, vf[nt >> 1] + (nt & 1) * 2);
            }
            __syncwarp();
        }
        __syncthreads();
    }

    const float i0 = 1.f / l0, i1 = 1.f / l1;
    #pragma unroll
    for (int nt = 0; nt < 8; nt++) {
        const int col = h * HDIM + nt * 8 + c0off;
        *(uint32_t*)(out + (size_t)(b * Tlen + r0g) * HID + col) =
            f2h2(O[nt][0] * i0, O[nt][1] * i0);
        *(uint32_t*)(out + (size_t)(b * Tlen + r1g) * HID + col) =
            f2h2(O[nt][2] * i1, O[nt][3] * i1);
    }
}

// ---------------------------------------------------------------------------
// Fused pre-pass: one launch does x->fp16 round + both weight transposes.
// Block ranges: [0,4096) round x; [4096,7168) Wqkv^T; [7168,8192) Wproj^T.
// ---------------------------------------------------------------------------
__global__ __launch_bounds__(256) void prepass(
    const float* __restrict__ x,
    const float* __restrict__ Wqkv, const float* __restrict__ Wproj,
    __half* __restrict__ xh,
    __half* __restrict__ wtqkv, __half* __restrict__ wtproj)
{
    const int bx = blockIdx.x, tid = threadIdx.x;
    if (bx < 4096) {                      // round x: 1M float4
        int i = bx * 256 + tid;
        float4 v = ((const float4*)x)[i];
        uint2 o;
        o.x = f2h2(v.x, v.y);
        o.y = f2h2(v.z, v.w);
        ((uint2*)xh)[i] = o;
        return;
    }
    __shared__ float tile[32][33];
    const float* in;
    __half* out;
    int K, N, n0, k0;
    if (bx < 7168) {                      // Wqkv: [1024][3072] -> [3072][1024]
        int b2 = bx - 4096;
        in = Wqkv; out = wtqkv; K = HID; N = C3;
        n0 = (b2 % 96) * 32; k0 = (b2 / 96) * 32;
    } else {                              // Wproj: [1024][1024]
        int b2 = bx - 7168;
        in = Wproj; out = wtproj; K = HID; N = HID;
        n0 = (b2 % 32) * 32; k0 = (b2 / 32) * 32;
    }
    const int tx = tid & 31, ty = tid >> 5;   // 32 x 8
    #pragma unroll
    for (int i = 0; i < 32; i += 8)
        tile[ty + i][tx] = in[(size_t)(k0 + ty + i) * N + n0 + tx];
    __syncthreads();
    #pragma unroll
    for (int i = 0; i < 32; i += 8)
        out[(size_t)(n0 + ty + i) * K + k0 + tx] = __float2half(tile[tx][ty + i]);
}

// ---------------------------------------------------------------------------
// Launch
// ---------------------------------------------------------------------------
extern "C" void kernel_launch(void* const* d_in, const int* in_sizes, int n_in,
                              void* d_out, int out_size)
{
    const float* x     = (const float*)d_in[0];
    const float* Wqkv  = (const float*)d_in[1];
    const float* bqkv  = (const float*)d_in[2];
    const float* Wproj = (const float*)d_in[3];
    const float* bproj = (const float*)d_in[4];
    float* out = (float*)d_out;

    __half *qkv_p, *att_p, *xh_p, *wtqkv_p, *wtproj_p;
    cudaGetSymbolAddress((void**)&qkv_p,    g_qkv);
    cudaGetSymbolAddress((void**)&att_p,    g_att);
    cudaGetSymbolAddress((void**)&xh_p,     g_xh);
    cudaGetSymbolAddress((void**)&wtqkv_p,  g_wtqkv);
    cudaGetSymbolAddress((void**)&wtproj_p, g_wtproj);

    cudaFuncSetAttribute(gemm_f16mma,
                         cudaFuncAttributeMaxDynamicSharedMemorySize, G_SMEM);
    cudaFuncSetAttribute(flash_mma,
                         cudaFuncAttributeMaxDynamicSharedMemorySize, FA_SMEM);

    // 0) fused pre-pass
    prepass<<<8192, 256>>>(x, Wqkv, Wproj, xh_p, wtqkv_p, wtproj_p);
    // 1) qkv = xh @ Wqkv^T + b  -> fp16
    gemm_f16mma<<<dim3(C3 / 128, BT / 128), 256, G_SMEM>>>(
        xh_p, wtqkv_p, bqkv, qkv_p, BT, C3, HID, 1);
    // 2) tensor-core causal flash attention -> fp16 (V^T via ldsm.trans)
    flash_mma<<<dim3(Tlen / 128, Bsz * HEADS), 256, FA_SMEM>>>(qkv_p, att_p);
    // 3) out = att @ Wproj^T + b -> f32
    gemm_f16mma<<<dim3(HID / 128, BT / 128), 256, G_SMEM>>>(
        att_p, wtproj_p, bproj, out, BT, HID, HID, 0);
}